// round 4
// baseline (speedup 1.0000x reference)
#include <cuda_runtime.h>
#include <cstddef>

// Problem constants
#define Bc  16
#define Sc  512
#define Dc  1024
#define Hc  16
#define DKc 64
#define Mc  8192   // B*S
#define Gc  8192   // H*S (gate projection width)

// Output layout inside d_out (float32):
//   out    : [16,512,1024]      ->  8388608 elems at offset 0
//   attn   : [16,16,512,512]    -> 67108864 elems at offset 8388608
//   scores : [16,16,512,512]    -> 67108864 elems at offset 75497472
#define OUT_ELEMS  8388608LL
#define ATTN_ELEMS 67108864LL

// -------------------- device scratch (static globals; no allocs) -----------
__device__ float g_q  [(size_t)Mc * Dc];   // 33.5 MB
__device__ float g_k  [(size_t)Mc * Dc];   // 33.5 MB
__device__ float g_v  [(size_t)Mc * Dc];   // 33.5 MB
__device__ float g_gt [(size_t)Mc * Gc];   // 268 MB gate matrix [b*S+s][h*S+k]
__device__ float g_ctx[(size_t)Mc * Dc];   // 33.5 MB attn@v, layout [b*S+q][h*DK+d]

// -------------------- generic SGEMM: C = A[MxK] @ B[KxN] + bias ------------
// BM=128, BN=128, BK=16, 256 threads, 8x8 per thread. M%128==0, N%128==0, K%16==0.
__global__ void __launch_bounds__(256)
sgemm_bias(const float* __restrict__ A, const float* __restrict__ Bm,
           const float* __restrict__ bias, float* __restrict__ C,
           int M, int N, int K)
{
    __shared__ float As[16][128];   // [kk][m]
    __shared__ float Bs[16][128];   // [kk][n]

    const int tid  = threadIdx.x;
    const int tx   = tid & 15;      // 0..15 -> 8 cols each
    const int ty   = tid >> 4;      // 0..15 -> 8 rows each
    const int row0 = blockIdx.y * 128;
    const int col0 = blockIdx.x * 128;

    // A tile loaders: 128 rows x 16 cols = 512 float4, 2 per thread
    const int a_r = tid >> 2;           // 0..63 (+64)
    const int a_c = (tid & 3) << 2;     // 0,4,8,12
    // B tile loaders: 16 rows x 128 cols = 512 float4, 2 per thread
    const int b_r = tid >> 5;           // 0..7 (+8)
    const int b_c = (tid & 31) << 2;    // 0..124

    float acc[8][8] = {};

    for (int k0 = 0; k0 < K; k0 += 16) {
        #pragma unroll
        for (int p = 0; p < 2; p++) {
            const int r = a_r + p * 64;
            const float4 v = *(const float4*)(A + (size_t)(row0 + r) * K + k0 + a_c);
            As[a_c + 0][r] = v.x; As[a_c + 1][r] = v.y;
            As[a_c + 2][r] = v.z; As[a_c + 3][r] = v.w;
        }
        #pragma unroll
        for (int p = 0; p < 2; p++) {
            const int r = b_r + p * 8;
            *(float4*)(&Bs[r][b_c]) =
                *(const float4*)(Bm + (size_t)(k0 + r) * N + col0 + b_c);
        }
        __syncthreads();

        #pragma unroll
        for (int kk = 0; kk < 16; kk++) {
            float4 a0 = *(const float4*)(&As[kk][ty * 8]);
            float4 a1 = *(const float4*)(&As[kk][ty * 8 + 4]);
            float4 b0 = *(const float4*)(&Bs[kk][tx * 8]);
            float4 b1 = *(const float4*)(&Bs[kk][tx * 8 + 4]);
            const float ar[8] = {a0.x, a0.y, a0.z, a0.w, a1.x, a1.y, a1.z, a1.w};
            const float br[8] = {b0.x, b0.y, b0.z, b0.w, b1.x, b1.y, b1.z, b1.w};
            #pragma unroll
            for (int i = 0; i < 8; i++)
                #pragma unroll
                for (int j = 0; j < 8; j++)
                    acc[i][j] = fmaf(ar[i], br[j], acc[i][j]);
        }
        __syncthreads();
    }

    #pragma unroll
    for (int i = 0; i < 8; i++) {
        const int row = row0 + ty * 8 + i;
        #pragma unroll
        for (int j = 0; j < 8; j += 4) {
            const int col = col0 + tx * 8 + j;
            const float4 bv = *(const float4*)(bias + col);
            float4 o;
            o.x = acc[i][j + 0] + bv.x;
            o.y = acc[i][j + 1] + bv.y;
            o.z = acc[i][j + 2] + bv.z;
            o.w = acc[i][j + 3] + bv.w;
            *(float4*)(C + (size_t)row * N + col) = o;
        }
    }
}

// -------------------- scores = q @ k^T * scale + prev ----------------------
// grid (8 n-tiles, 8 q-tiles, 256 bh), 256 threads, 64x64 tile, K=64.
__global__ void __launch_bounds__(256)
scores_kernel(const float* __restrict__ prev, const float* __restrict__ scale_p,
              float* __restrict__ scores)
{
    const int bh = blockIdx.z;
    const int b  = bh >> 4;
    const int h  = bh & 15;
    const int q0 = blockIdx.y * 64;
    const int n0 = blockIdx.x * 64;

    __shared__ float Qs[64][64];   // [kk][m]
    __shared__ float Ks[64][64];   // [kk][n]

    const int tid = threadIdx.x;
    const int lr  = tid >> 4;            // 0..15
    const int lc  = (tid & 15) << 2;     // 0..60

    #pragma unroll
    for (int p = 0; p < 4; p++) {
        const int m = lr + p * 16;
        const float4 qv = *(const float4*)(&g_q[(size_t)(b * Sc + q0 + m) * Dc + h * DKc + lc]);
        Qs[lc + 0][m] = qv.x; Qs[lc + 1][m] = qv.y;
        Qs[lc + 2][m] = qv.z; Qs[lc + 3][m] = qv.w;
        const float4 kv = *(const float4*)(&g_k[(size_t)(b * Sc + n0 + m) * Dc + h * DKc + lc]);
        Ks[lc + 0][m] = kv.x; Ks[lc + 1][m] = kv.y;
        Ks[lc + 2][m] = kv.z; Ks[lc + 3][m] = kv.w;
    }
    __syncthreads();

    const int tx = tid & 15;
    const int ty = tid >> 4;
    float acc[4][4] = {};

    #pragma unroll
    for (int kk = 0; kk < 64; kk++) {
        const float4 a4 = *(const float4*)(&Qs[kk][ty * 4]);
        const float4 b4 = *(const float4*)(&Ks[kk][tx * 4]);
        const float ar[4] = {a4.x, a4.y, a4.z, a4.w};
        const float br[4] = {b4.x, b4.y, b4.z, b4.w};
        #pragma unroll
        for (int i = 0; i < 4; i++)
            #pragma unroll
            for (int j = 0; j < 4; j++)
                acc[i][j] = fmaf(ar[i], br[j], acc[i][j]);
    }

    const float scale = *scale_p;
    const size_t base = ((size_t)(b * Hc + h) * Sc) * Sc;
    #pragma unroll
    for (int i = 0; i < 4; i++) {
        const size_t off = base + (size_t)(q0 + ty * 4 + i) * Sc + n0 + tx * 4;
        const float4 pv = *(const float4*)(prev + off);
        float4 o;
        o.x = fmaf(acc[i][0], scale, pv.x);
        o.y = fmaf(acc[i][1], scale, pv.y);
        o.z = fmaf(acc[i][2], scale, pv.z);
        o.w = fmaf(acc[i][3], scale, pv.w);
        *(float4*)(scores + off) = o;
    }
}

// -------------------- attn = gate * softmax(scores, axis=-1) ---------------
// one warp per 512-wide row; 256 threads = 8 rows/block; grid = 131072/8.
__global__ void __launch_bounds__(256)
softmax_gate_kernel(float* __restrict__ attn, const float* __restrict__ scores)
{
    const int warp = threadIdx.x >> 5;
    const int lane = threadIdx.x & 31;
    const long long row = (long long)blockIdx.x * 8 + warp;  // (b*H+h)*S + q

    const float* srow = scores + row * Sc;
    float*       arow = attn   + row * Sc;

    const int b  = (int)(row >> 13);     // / (H*S)
    const int hq = (int)(row & 8191);
    const int h  = hq >> 9;
    const int q  = hq & 511;
    const float* grow = g_gt + (size_t)(b * Sc + q) * Gc + (size_t)h * Sc;

    float4 x[4];
    float mx = -3.402823466e38f;
    #pragma unroll
    for (int t = 0; t < 4; t++) {
        x[t] = *(const float4*)(srow + t * 128 + lane * 4);
        mx = fmaxf(mx, fmaxf(fmaxf(x[t].x, x[t].y), fmaxf(x[t].z, x[t].w)));
    }
    #pragma unroll
    for (int o = 16; o > 0; o >>= 1)
        mx = fmaxf(mx, __shfl_xor_sync(0xffffffffu, mx, o));

    float sum = 0.0f;
    #pragma unroll
    for (int t = 0; t < 4; t++) {
        x[t].x = __expf(x[t].x - mx);
        x[t].y = __expf(x[t].y - mx);
        x[t].z = __expf(x[t].z - mx);
        x[t].w = __expf(x[t].w - mx);
        sum += (x[t].x + x[t].y) + (x[t].z + x[t].w);
    }
    #pragma unroll
    for (int o = 16; o > 0; o >>= 1)
        sum += __shfl_xor_sync(0xffffffffu, sum, o);
    const float inv = 1.0f / sum;

    #pragma unroll
    for (int t = 0; t < 4; t++) {
        const float4 gv = *(const float4*)(grow + t * 128 + lane * 4);
        float4 o;
        o.x = gv.x * x[t].x * inv;
        o.y = gv.y * x[t].y * inv;
        o.z = gv.z * x[t].z * inv;
        o.w = gv.w * x[t].w * inv;
        *(float4*)(arow + t * 128 + lane * 4) = o;
    }
}

// -------------------- ctx = attn @ v  (per b,h: [512,512]x[512,64]) --------
// grid (8 q-tiles, 256 bh), 256 threads, 64x64 tile, K loop over 512.
__global__ void __launch_bounds__(256)
ctx_kernel(const float* __restrict__ attn)
{
    const int bh = blockIdx.y;
    const int b  = bh >> 4;
    const int h  = bh & 15;
    const int q0 = blockIdx.x * 64;

    __shared__ float As[64][64];   // [kk][m]  attn^T tile
    __shared__ float Vs[64][64];   // [kk][n]  v tile

    const int tid = threadIdx.x;
    const int lr  = tid >> 4;
    const int lc  = (tid & 15) << 2;
    const int tx  = tid & 15;
    const int ty  = tid >> 4;

    const size_t abase = ((size_t)(b * Hc + h) * Sc + q0) * Sc;
    float acc[4][4] = {};

    for (int kt = 0; kt < Sc; kt += 64) {
        #pragma unroll
        for (int p = 0; p < 4; p++) {
            const int m = lr + p * 16;
            const float4 av = *(const float4*)(attn + abase + (size_t)m * Sc + kt + lc);
            As[lc + 0][m] = av.x; As[lc + 1][m] = av.y;
            As[lc + 2][m] = av.z; As[lc + 3][m] = av.w;
            const float4 vv = *(const float4*)(&g_v[(size_t)(b * Sc + kt + m) * Dc + h * DKc + lc]);
            *(float4*)(&Vs[m][lc]) = vv;
        }
        __syncthreads();

        #pragma unroll
        for (int kk = 0; kk < 64; kk++) {
            const float4 a4 = *(const float4*)(&As[kk][ty * 4]);
            const float4 b4 = *(const float4*)(&Vs[kk][tx * 4]);
            const float ar[4] = {a4.x, a4.y, a4.z, a4.w};
            const float br[4] = {b4.x, b4.y, b4.z, b4.w};
            #pragma unroll
            for (int i = 0; i < 4; i++)
                #pragma unroll
                for (int j = 0; j < 4; j++)
                    acc[i][j] = fmaf(ar[i], br[j], acc[i][j]);
        }
        __syncthreads();
    }

    #pragma unroll
    for (int i = 0; i < 4; i++) {
        const int q = q0 + ty * 4 + i;
        float4 o;
        o.x = acc[i][0]; o.y = acc[i][1]; o.z = acc[i][2]; o.w = acc[i][3];
        *(float4*)(&g_ctx[(size_t)(b * Sc + q) * Dc + h * DKc + tx * 4]) = o;
    }
}

// ---------------------------------------------------------------------------
extern "C" void kernel_launch(void* const* d_in, const int* in_sizes, int n_in,
                              void* d_out, int out_size)
{
    (void)in_sizes; (void)n_in; (void)out_size;

    const float* Q     = (const float*)d_in[0];
    const float* prev  = (const float*)d_in[1];
    const float* Wq    = (const float*)d_in[2];
    const float* bq    = (const float*)d_in[3];
    const float* Wk    = (const float*)d_in[4];
    const float* bk    = (const float*)d_in[5];
    const float* Wv    = (const float*)d_in[6];
    const float* bv    = (const float*)d_in[7];
    const float* Wg    = (const float*)d_in[8];
    const float* bg    = (const float*)d_in[9];
    const float* Wo    = (const float*)d_in[10];
    const float* bo    = (const float*)d_in[11];
    const float* scale = (const float*)d_in[12];

    float* out    = (float*)d_out;
    float* attn   = out + OUT_ELEMS;
    float* scores = attn + ATTN_ELEMS;

    float *qb, *kb, *vb, *gb, *cb;
    cudaGetSymbolAddress((void**)&qb, g_q);
    cudaGetSymbolAddress((void**)&kb, g_k);
    cudaGetSymbolAddress((void**)&vb, g_v);
    cudaGetSymbolAddress((void**)&gb, g_gt);
    cudaGetSymbolAddress((void**)&cb, g_ctx);

    // Projections: M=8192, K=1024
    sgemm_bias<<<dim3(Dc / 128, Mc / 128), 256>>>(Q, Wq, bq, qb, Mc, Dc, Dc);
    sgemm_bias<<<dim3(Dc / 128, Mc / 128), 256>>>(Q, Wk, bk, kb, Mc, Dc, Dc);
    sgemm_bias<<<dim3(Dc / 128, Mc / 128), 256>>>(Q, Wv, bv, vb, Mc, Dc, Dc);
    sgemm_bias<<<dim3(Gc / 128, Mc / 128), 256>>>(Q, Wg, bg, gb, Mc, Gc, Dc);

    // scores = q k^T * scale + prev   -> d_out scores region
    scores_kernel<<<dim3(8, 8, Bc * Hc), 256>>>(prev, scale, scores);

    // attn = gate * softmax(scores)   -> d_out attn region
    softmax_gate_kernel<<<(Bc * Hc * Sc) / 8, 256>>>(attn, scores);

    // ctx = attn @ v  -> g_ctx ([b*S+q][h*DK+d])
    ctx_kernel<<<dim3(8, Bc * Hc), 256>>>(attn);

    // out = ctx @ Wo + bo -> d_out out region
    sgemm_bias<<<dim3(Dc / 128, Mc / 128), 256>>>(cb, Wo, bo, out, Mc, Dc, Dc);
}

// round 6
// speedup vs baseline: 2.1145x; 2.1145x over previous
#include <cuda_runtime.h>
#include <cuda_bf16.h>
#include <cstdint>
#include <cstddef>

// Problem constants
#define Bc  16
#define Sc  512
#define Dc  1024
#define Hc  16
#define DKc 64
#define Mc  8192   // B*S
#define Gc  8192   // H*S

#define OUT_ELEMS  8388608LL
#define ATTN_ELEMS 67108864LL

// -------------------- device scratch (static globals; no allocs) -----------
__device__ float g_q  [(size_t)Mc * Dc];
__device__ float g_k  [(size_t)Mc * Dc];
__device__ float g_v  [(size_t)Mc * Dc];
__device__ float g_gt [(size_t)Mc * Gc];   // gate [b*S+s][h*S+k] fp32
__device__ float g_ctx[(size_t)Mc * Dc];   // attn@v fp32
// bf16 split operands
__device__ __nv_bfloat16 g_ah[(size_t)Mc * Dc];  // activation hi  [M,K]
__device__ __nv_bfloat16 g_al[(size_t)Mc * Dc];  // activation lo
__device__ __nv_bfloat16 g_wh[(size_t)Gc * Dc];  // weight^T hi [N,K]
__device__ __nv_bfloat16 g_wl[(size_t)Gc * Dc];  // weight^T lo

// ===================== PTX helpers (sm_80-level only) ======================
__device__ __forceinline__ uint32_t smem_u32(const void* p) {
    uint32_t a;
    asm("{ .reg .u64 t; cvta.to.shared.u64 t, %1; cvt.u32.u64 %0, t; }" : "=r"(a) : "l"(p));
    return a;
}
__device__ __forceinline__ void cp16(uint32_t smem, const void* g) {
    asm volatile("cp.async.cg.shared.global [%0], [%1], 16;\n" :: "r"(smem), "l"(g));
}
#define CP_COMMIT() asm volatile("cp.async.commit_group;" ::: "memory")
#define CP_WAIT0()  asm volatile("cp.async.wait_group 0;" ::: "memory")

#define LDSM4(r0, r1, r2, r3, addr) \
    asm volatile("ldmatrix.sync.aligned.m8n8.x4.shared.b16 {%0,%1,%2,%3}, [%4];" \
        : "=r"(r0), "=r"(r1), "=r"(r2), "=r"(r3) : "r"(addr))

#define MMA_BF16(d, a, b) \
    asm volatile("mma.sync.aligned.m16n8k16.row.col.f32.bf16.bf16.f32 " \
        "{%0,%1,%2,%3},{%4,%5,%6,%7},{%8,%9},{%0,%1,%2,%3};" \
        : "+f"((d)[0]), "+f"((d)[1]), "+f"((d)[2]), "+f"((d)[3]) \
        : "r"((a)[0]), "r"((a)[1]), "r"((a)[2]), "r"((a)[3]), \
          "r"((b)[0]), "r"((b)[1]))

// ===================== conversion kernels ==================================
__global__ void __launch_bounds__(256)
split_kernel(const float* __restrict__ x, __nv_bfloat16* __restrict__ hi,
             __nv_bfloat16* __restrict__ lo, long long n4)
{
    long long i = ((long long)blockIdx.x * 256 + threadIdx.x);
    if (i >= n4) return;
    const float4 v = ((const float4*)x)[i];
    __nv_bfloat16 h0 = __float2bfloat16(v.x);
    __nv_bfloat16 h1 = __float2bfloat16(v.y);
    __nv_bfloat16 h2 = __float2bfloat16(v.z);
    __nv_bfloat16 h3 = __float2bfloat16(v.w);
    __nv_bfloat162 hh0; hh0.x = h0; hh0.y = h1;
    __nv_bfloat162 hh1; hh1.x = h2; hh1.y = h3;
    __nv_bfloat162 ll0;
    ll0.x = __float2bfloat16(v.x - __bfloat162float(h0));
    ll0.y = __float2bfloat16(v.y - __bfloat162float(h1));
    __nv_bfloat162 ll1;
    ll1.x = __float2bfloat16(v.z - __bfloat162float(h2));
    ll1.y = __float2bfloat16(v.w - __bfloat162float(h3));
    ((__nv_bfloat162*)hi)[i * 2 + 0] = hh0;
    ((__nv_bfloat162*)hi)[i * 2 + 1] = hh1;
    ((__nv_bfloat162*)lo)[i * 2 + 0] = ll0;
    ((__nv_bfloat162*)lo)[i * 2 + 1] = ll1;
}

// W[K][N] fp32 -> T[N][K] bf16 hi/lo
__global__ void __launch_bounds__(256)
transpose_split(const float* __restrict__ W, __nv_bfloat16* __restrict__ Th,
                __nv_bfloat16* __restrict__ Tl, int K, int N)
{
    __shared__ float t[32][33];
    const int n0 = blockIdx.x * 32, k0 = blockIdx.y * 32;
    const int tx = threadIdx.x, ty = threadIdx.y;  // (32, 8)
    #pragma unroll
    for (int p = 0; p < 4; p++) {
        const int kk = ty + p * 8;
        t[kk][tx] = W[(size_t)(k0 + kk) * N + n0 + tx];
    }
    __syncthreads();
    #pragma unroll
    for (int p = 0; p < 4; p++) {
        const int nn = ty + p * 8;
        const float v = t[tx][nn];
        const __nv_bfloat16 h = __float2bfloat16(v);
        Th[(size_t)(n0 + nn) * K + k0 + tx] = h;
        Tl[(size_t)(n0 + nn) * K + k0 + tx] = __float2bfloat16(v - __bfloat162float(h));
    }
}

// ===================== mma.sync split-bf16 GEMM ============================
// C[M,N] = Ah@Bh^T + Ah@Bl^T + Al@Bh^T + bias   (A:[M,K], B:[N,K] bf16)
// BM=128, BN=128, BK=32. 256 threads = 8 warps (4 M x 2 N), warp tile 32x64.
// Smem rows padded to 80B: ldmatrix row banks {0,20,8,28,16,4,24,12} -> no conflicts.
#define RS 80
#define TILE_B   (128 * RS)          // 10240 per operand tile
#define STAGE_B  (4 * TILE_B)        // Ah | Al | Bh | Bl = 40960
#define GEMM_SMEM (2 * STAGE_B)      // 81920

__global__ void __launch_bounds__(256, 2)
gemm_mma(const __nv_bfloat16* __restrict__ Ah, const __nv_bfloat16* __restrict__ Al,
         const __nv_bfloat16* __restrict__ Bh, const __nv_bfloat16* __restrict__ Bl,
         const float* __restrict__ bias, float* __restrict__ C,
         int Ntot, int K)
{
    extern __shared__ char dsm[];
    const uint32_t sb0 = smem_u32(dsm);
    const int tid  = threadIdx.x;
    const int lane = tid & 31;
    const int wid  = tid >> 5;
    const int wm   = wid & 3;        // 4 warps along M (32 rows each)
    const int wn   = wid >> 2;       // 2 warps along N (64 cols each)
    const int m0   = blockIdx.y * 128;
    const int n0   = blockIdx.x * 128;

    const size_t Kb = (size_t)K * 2;     // global row stride (bytes)
    const int NK = K >> 5;               // BK = 32

    const char* pAh = (const char*)Ah + (size_t)m0 * Kb;
    const char* pAl = (const char*)Al + (size_t)m0 * Kb;
    const char* pBh = (const char*)Bh + (size_t)n0 * Kb;
    const char* pBl = (const char*)Bl + (size_t)n0 * Kb;

    // stage loader: 128 rows x 64B per operand tile; 2 chunks/thread/tile
    auto load_stage = [&](int kt, int s) {
        const uint32_t sb = sb0 + (uint32_t)s * STAGE_B;
        const size_t kb = (size_t)kt * 64;
        #pragma unroll
        for (int i = 0; i < 2; i++) {
            const int c   = tid + i * 256;
            const int row = c >> 2;
            const int seg = (c & 3) * 16;
            const uint32_t so = (uint32_t)(row * RS + seg);
            const size_t go = (size_t)row * Kb + kb + seg;
            cp16(sb + so,              pAh + go);
            cp16(sb + TILE_B + so,     pAl + go);
            cp16(sb + 2 * TILE_B + so, pBh + go);
            cp16(sb + 3 * TILE_B + so, pBl + go);
        }
    };

    // ldmatrix lane addressing
    const uint32_t aRow  = (uint32_t)(wm * 32 + (lane & 15));
    const uint32_t aByte = (uint32_t)((lane >> 4) * 16);
    const uint32_t bRow  = (uint32_t)(wn * 64 + (lane & 7) + ((lane >> 4) & 1) * 8);
    const uint32_t bByte = (uint32_t)(((lane >> 3) & 1) * 16);

    float acc[2][8][4] = {};

    load_stage(0, 0); CP_COMMIT();

    for (int kt = 0; kt < NK; kt++) {
        const int s = kt & 1;
        CP_WAIT0();
        __syncthreads();
        if (kt + 1 < NK) { load_stage(kt + 1, s ^ 1); CP_COMMIT(); }

        const uint32_t sb = sb0 + (uint32_t)s * STAGE_B;

        #pragma unroll
        for (int kk = 0; kk < 2; kk++) {
            uint32_t ah[2][4], al[2][4];
            #pragma unroll
            for (int mi = 0; mi < 2; mi++) {
                const uint32_t ad = sb + (aRow + mi * 16) * RS + kk * 32 + aByte;
                LDSM4(ah[mi][0], ah[mi][1], ah[mi][2], ah[mi][3], ad);
                LDSM4(al[mi][0], al[mi][1], al[mi][2], al[mi][3], ad + TILE_B);
            }
            // B in two halves of 4 n-tiles each (register pressure)
            #pragma unroll
            for (int half = 0; half < 2; half++) {
                uint32_t bh[4][2], bl[4][2];
                #pragma unroll
                for (int p = 0; p < 2; p++) {
                    const uint32_t bd = sb + 2 * TILE_B +
                        (bRow + (half * 2 + p) * 16) * RS + kk * 32 + bByte;
                    uint32_t t0, t1, t2, t3;
                    LDSM4(t0, t1, t2, t3, bd);
                    bh[2 * p][0] = t0; bh[2 * p][1] = t1;
                    bh[2 * p + 1][0] = t2; bh[2 * p + 1][1] = t3;
                    LDSM4(t0, t1, t2, t3, bd + TILE_B);
                    bl[2 * p][0] = t0; bl[2 * p][1] = t1;
                    bl[2 * p + 1][0] = t2; bl[2 * p + 1][1] = t3;
                }
                #pragma unroll
                for (int mi = 0; mi < 2; mi++)
                    #pragma unroll
                    for (int nj = 0; nj < 4; nj++) {
                        float* d = acc[mi][half * 4 + nj];
                        MMA_BF16(d, ah[mi], bh[nj]);
                        MMA_BF16(d, ah[mi], bl[nj]);
                        MMA_BF16(d, al[mi], bh[nj]);
                    }
            }
        }
    }

    // Epilogue: fragment (mi, ni): rows m0+wm*32+mi*16+{trow, trow+8}, cols +tc
    const int trow = lane >> 2;
    const int tc   = (lane & 3) * 2;
    #pragma unroll
    for (int mi = 0; mi < 2; mi++) {
        const int r = m0 + wm * 32 + mi * 16 + trow;
        #pragma unroll
        for (int ni = 0; ni < 8; ni++) {
            const int col = n0 + wn * 64 + ni * 8 + tc;
            const float2 bv = *(const float2*)(bias + col);
            float2 o0, o1;
            o0.x = acc[mi][ni][0] + bv.x; o0.y = acc[mi][ni][1] + bv.y;
            o1.x = acc[mi][ni][2] + bv.x; o1.y = acc[mi][ni][3] + bv.y;
            *(float2*)(C + (size_t)r * Ntot + col) = o0;
            *(float2*)(C + (size_t)(r + 8) * Ntot + col) = o1;
        }
    }
}

// ===================== attention kernels (SIMT) =============================
__global__ void __launch_bounds__(256)
scores_kernel(const float* __restrict__ prev, const float* __restrict__ scale_p,
              float* __restrict__ scores)
{
    const int bh = blockIdx.z;
    const int b  = bh >> 4;
    const int h  = bh & 15;
    const int q0 = blockIdx.y * 64;
    const int n0 = blockIdx.x * 64;

    __shared__ float Qs[64][64];
    __shared__ float Ks[64][64];

    const int tid = threadIdx.x;
    const int lr  = tid >> 4;
    const int lc  = (tid & 15) << 2;

    #pragma unroll
    for (int p = 0; p < 4; p++) {
        const int m = lr + p * 16;
        const float4 qv = *(const float4*)(&g_q[(size_t)(b * Sc + q0 + m) * Dc + h * DKc + lc]);
        Qs[lc + 0][m] = qv.x; Qs[lc + 1][m] = qv.y;
        Qs[lc + 2][m] = qv.z; Qs[lc + 3][m] = qv.w;
        const float4 kv = *(const float4*)(&g_k[(size_t)(b * Sc + n0 + m) * Dc + h * DKc + lc]);
        Ks[lc + 0][m] = kv.x; Ks[lc + 1][m] = kv.y;
        Ks[lc + 2][m] = kv.z; Ks[lc + 3][m] = kv.w;
    }
    __syncthreads();

    const int tx = tid & 15;
    const int ty = tid >> 4;
    float acc[4][4] = {};

    #pragma unroll
    for (int kk = 0; kk < 64; kk++) {
        const float4 a4 = *(const float4*)(&Qs[kk][ty * 4]);
        const float4 b4 = *(const float4*)(&Ks[kk][tx * 4]);
        const float ar[4] = {a4.x, a4.y, a4.z, a4.w};
        const float br[4] = {b4.x, b4.y, b4.z, b4.w};
        #pragma unroll
        for (int i = 0; i < 4; i++)
            #pragma unroll
            for (int j = 0; j < 4; j++)
                acc[i][j] = fmaf(ar[i], br[j], acc[i][j]);
    }

    const float scale = *scale_p;
    const size_t base = ((size_t)(b * Hc + h) * Sc) * Sc;
    #pragma unroll
    for (int i = 0; i < 4; i++) {
        const size_t off = base + (size_t)(q0 + ty * 4 + i) * Sc + n0 + tx * 4;
        const float4 pv = *(const float4*)(prev + off);
        float4 o;
        o.x = fmaf(acc[i][0], scale, pv.x);
        o.y = fmaf(acc[i][1], scale, pv.y);
        o.z = fmaf(acc[i][2], scale, pv.z);
        o.w = fmaf(acc[i][3], scale, pv.w);
        *(float4*)(scores + off) = o;
    }
}

__global__ void __launch_bounds__(256)
softmax_gate_kernel(float* __restrict__ attn, const float* __restrict__ scores)
{
    const int warp = threadIdx.x >> 5;
    const int lane = threadIdx.x & 31;
    const long long row = (long long)blockIdx.x * 8 + warp;

    const float* srow = scores + row * Sc;
    float*       arow = attn   + row * Sc;

    const int b  = (int)(row >> 13);
    const int hq = (int)(row & 8191);
    const int h  = hq >> 9;
    const int q  = hq & 511;
    const float* grow = g_gt + (size_t)(b * Sc + q) * Gc + (size_t)h * Sc;

    float4 x[4];
    float mx = -3.402823466e38f;
    #pragma unroll
    for (int t = 0; t < 4; t++) {
        x[t] = *(const float4*)(srow + t * 128 + lane * 4);
        mx = fmaxf(mx, fmaxf(fmaxf(x[t].x, x[t].y), fmaxf(x[t].z, x[t].w)));
    }
    #pragma unroll
    for (int o = 16; o > 0; o >>= 1)
        mx = fmaxf(mx, __shfl_xor_sync(0xffffffffu, mx, o));

    float sum = 0.0f;
    #pragma unroll
    for (int t = 0; t < 4; t++) {
        x[t].x = __expf(x[t].x - mx);
        x[t].y = __expf(x[t].y - mx);
        x[t].z = __expf(x[t].z - mx);
        x[t].w = __expf(x[t].w - mx);
        sum += (x[t].x + x[t].y) + (x[t].z + x[t].w);
    }
    #pragma unroll
    for (int o = 16; o > 0; o >>= 1)
        sum += __shfl_xor_sync(0xffffffffu, sum, o);
    const float inv = 1.0f / sum;

    #pragma unroll
    for (int t = 0; t < 4; t++) {
        const float4 gv = *(const float4*)(grow + t * 128 + lane * 4);
        float4 o;
        o.x = gv.x * x[t].x * inv;
        o.y = gv.y * x[t].y * inv;
        o.z = gv.z * x[t].z * inv;
        o.w = gv.w * x[t].w * inv;
        *(float4*)(arow + t * 128 + lane * 4) = o;
    }
}

__global__ void __launch_bounds__(256)
ctx_kernel(const float* __restrict__ attn)
{
    const int bh = blockIdx.y;
    const int b  = bh >> 4;
    const int h  = bh & 15;
    const int q0 = blockIdx.x * 64;

    __shared__ float As[64][64];
    __shared__ float Vs[64][64];

    const int tid = threadIdx.x;
    const int lr  = tid >> 4;
    const int lc  = (tid & 15) << 2;
    const int tx  = tid & 15;
    const int ty  = tid >> 4;

    const size_t abase = ((size_t)(b * Hc + h) * Sc + q0) * Sc;
    float acc[4][4] = {};

    for (int kt = 0; kt < Sc; kt += 64) {
        #pragma unroll
        for (int p = 0; p < 4; p++) {
            const int m = lr + p * 16;
            const float4 av = *(const float4*)(attn + abase + (size_t)m * Sc + kt + lc);
            As[lc + 0][m] = av.x; As[lc + 1][m] = av.y;
            As[lc + 2][m] = av.z; As[lc + 3][m] = av.w;
            const float4 vv = *(const float4*)(&g_v[(size_t)(b * Sc + kt + m) * Dc + h * DKc + lc]);
            *(float4*)(&Vs[m][lc]) = vv;
        }
        __syncthreads();

        #pragma unroll
        for (int kk = 0; kk < 64; kk++) {
            const float4 a4 = *(const float4*)(&As[kk][ty * 4]);
            const float4 b4 = *(const float4*)(&Vs[kk][tx * 4]);
            const float ar[4] = {a4.x, a4.y, a4.z, a4.w};
            const float br[4] = {b4.x, b4.y, b4.z, b4.w};
            #pragma unroll
            for (int i = 0; i < 4; i++)
                #pragma unroll
                for (int j = 0; j < 4; j++)
                    acc[i][j] = fmaf(ar[i], br[j], acc[i][j]);
        }
        __syncthreads();
    }

    #pragma unroll
    for (int i = 0; i < 4; i++) {
        const int q = q0 + ty * 4 + i;
        float4 o;
        o.x = acc[i][0]; o.y = acc[i][1]; o.z = acc[i][2]; o.w = acc[i][3];
        *(float4*)(&g_ctx[(size_t)(b * Sc + q) * Dc + h * DKc + tx * 4]) = o;
    }
}

// ---------------------------------------------------------------------------
extern "C" void kernel_launch(void* const* d_in, const int* in_sizes, int n_in,
                              void* d_out, int out_size)
{
    (void)in_sizes; (void)n_in; (void)out_size;

    const float* Q     = (const float*)d_in[0];
    const float* prev  = (const float*)d_in[1];
    const float* Wq    = (const float*)d_in[2];
    const float* bq    = (const float*)d_in[3];
    const float* Wk    = (const float*)d_in[4];
    const float* bk    = (const float*)d_in[5];
    const float* Wv    = (const float*)d_in[6];
    const float* bv    = (const float*)d_in[7];
    const float* Wg    = (const float*)d_in[8];
    const float* bg    = (const float*)d_in[9];
    const float* Wo    = (const float*)d_in[10];
    const float* bo    = (const float*)d_in[11];
    const float* scale = (const float*)d_in[12];

    float* out    = (float*)d_out;
    float* attn   = out + OUT_ELEMS;
    float* scores = attn + ATTN_ELEMS;

    float *qb, *kb, *vb, *gb, *cb;
    __nv_bfloat16 *ah, *al, *wh, *wl;
    cudaGetSymbolAddress((void**)&qb, g_q);
    cudaGetSymbolAddress((void**)&kb, g_k);
    cudaGetSymbolAddress((void**)&vb, g_v);
    cudaGetSymbolAddress((void**)&gb, g_gt);
    cudaGetSymbolAddress((void**)&cb, g_ctx);
    cudaGetSymbolAddress((void**)&ah, g_ah);
    cudaGetSymbolAddress((void**)&al, g_al);
    cudaGetSymbolAddress((void**)&wh, g_wh);
    cudaGetSymbolAddress((void**)&wl, g_wl);

    cudaFuncSetAttribute(gemm_mma, cudaFuncAttributeMaxDynamicSharedMemorySize, GEMM_SMEM);

    const dim3 tblk(32, 8);
    const long long nQ4 = (long long)Mc * Dc / 4;

    // split activations into bf16 hi/lo
    split_kernel<<<(int)(nQ4 / 256), 256>>>(Q, ah, al, nQ4);

    // q projection
    transpose_split<<<dim3(Dc / 32, Dc / 32), tblk>>>(Wq, wh, wl, Dc, Dc);
    gemm_mma<<<dim3(Dc / 128, Mc / 128), 256, GEMM_SMEM>>>(ah, al, wh, wl, bq, qb, Dc, Dc);
    // k projection
    transpose_split<<<dim3(Dc / 32, Dc / 32), tblk>>>(Wk, wh, wl, Dc, Dc);
    gemm_mma<<<dim3(Dc / 128, Mc / 128), 256, GEMM_SMEM>>>(ah, al, wh, wl, bk, kb, Dc, Dc);
    // v projection
    transpose_split<<<dim3(Dc / 32, Dc / 32), tblk>>>(Wv, wh, wl, Dc, Dc);
    gemm_mma<<<dim3(Dc / 128, Mc / 128), 256, GEMM_SMEM>>>(ah, al, wh, wl, bv, vb, Dc, Dc);
    // gate projection (N = 8192)
    transpose_split<<<dim3(Gc / 32, Dc / 32), tblk>>>(Wg, wh, wl, Dc, Gc);
    gemm_mma<<<dim3(Gc / 128, Mc / 128), 256, GEMM_SMEM>>>(ah, al, wh, wl, bg, gb, Gc, Dc);

    // scores = q k^T * scale + prev
    scores_kernel<<<dim3(8, 8, Bc * Hc), 256>>>(prev, scale, scores);
    // attn = gate * softmax(scores)
    softmax_gate_kernel<<<(Bc * Hc * Sc) / 8, 256>>>(attn, scores);
    // ctx = attn @ v
    ctx_kernel<<<dim3(8, Bc * Hc), 256>>>(attn);

    // out = ctx @ Wo + bo  (split ctx, reuse activation buffers)
    split_kernel<<<(int)(nQ4 / 256), 256>>>(cb, ah, al, nQ4);
    transpose_split<<<dim3(Dc / 32, Dc / 32), tblk>>>(Wo, wh, wl, Dc, Dc);
    gemm_mma<<<dim3(Dc / 128, Mc / 128), 256, GEMM_SMEM>>>(ah, al, wh, wl, bo, out, Dc, Dc);
}

// round 7
// speedup vs baseline: 2.6180x; 1.2381x over previous
#include <cuda_runtime.h>
#include <cuda_bf16.h>
#include <cstdint>
#include <cstddef>

// Problem constants
#define Bc  16
#define Sc  512
#define Dc  1024
#define Hc  16
#define DKc 64
#define Mc  8192   // B*S
#define Gc  8192   // H*S

#define OUT_ELEMS  8388608LL
#define ATTN_ELEMS 67108864LL

// -------------------- device scratch (static globals; no allocs) -----------
__device__ float g_gt [(size_t)Mc * Gc];          // gate [b*S+s][h*S+k] fp32
__device__ __nv_bfloat16 g_ah[(size_t)Mc * Dc];   // activation hi / later ctx hi
__device__ __nv_bfloat16 g_al[(size_t)Mc * Dc];   // activation lo / later ctx lo
__device__ __nv_bfloat16 g_wh[(size_t)Gc * Dc];   // weight^T hi [N,K]
__device__ __nv_bfloat16 g_wl[(size_t)Gc * Dc];   // weight^T lo
__device__ __nv_bfloat16 g_qh[(size_t)Mc * Dc];
__device__ __nv_bfloat16 g_ql[(size_t)Mc * Dc];
__device__ __nv_bfloat16 g_kh[(size_t)Mc * Dc];
__device__ __nv_bfloat16 g_kl[(size_t)Mc * Dc];
__device__ __nv_bfloat16 g_vh[(size_t)Mc * Dc];
__device__ __nv_bfloat16 g_vl[(size_t)Mc * Dc];

// ===================== PTX helpers (sm_80-level only) ======================
__device__ __forceinline__ uint32_t smem_u32(const void* p) {
    uint32_t a;
    asm("{ .reg .u64 t; cvta.to.shared.u64 t, %1; cvt.u32.u64 %0, t; }" : "=r"(a) : "l"(p));
    return a;
}
__device__ __forceinline__ void cp16(uint32_t smem, const void* g) {
    asm volatile("cp.async.cg.shared.global [%0], [%1], 16;\n" :: "r"(smem), "l"(g));
}
#define CP_COMMIT() asm volatile("cp.async.commit_group;" ::: "memory")
#define CP_WAIT0()  asm volatile("cp.async.wait_group 0;" ::: "memory")

#define LDSM4(r0, r1, r2, r3, addr) \
    asm volatile("ldmatrix.sync.aligned.m8n8.x4.shared.b16 {%0,%1,%2,%3}, [%4];" \
        : "=r"(r0), "=r"(r1), "=r"(r2), "=r"(r3) : "r"(addr))
#define LDSM4T(r0, r1, r2, r3, addr) \
    asm volatile("ldmatrix.sync.aligned.m8n8.x4.trans.shared.b16 {%0,%1,%2,%3}, [%4];" \
        : "=r"(r0), "=r"(r1), "=r"(r2), "=r"(r3) : "r"(addr))

#define MMA_BF16(d, a, b) \
    asm volatile("mma.sync.aligned.m16n8k16.row.col.f32.bf16.bf16.f32 " \
        "{%0,%1,%2,%3},{%4,%5,%6,%7},{%8,%9},{%0,%1,%2,%3};" \
        : "+f"((d)[0]), "+f"((d)[1]), "+f"((d)[2]), "+f"((d)[3]) \
        : "r"((a)[0]), "r"((a)[1]), "r"((a)[2]), "r"((a)[3]), \
          "r"((b)[0]), "r"((b)[1]))

__device__ __forceinline__ uint32_t pack_bf16_hi(float x, float y) {
    __nv_bfloat162 p;
    p.x = __float2bfloat16(x); p.y = __float2bfloat16(y);
    return *(uint32_t*)&p;
}

// ===================== conversion kernels ==================================
__global__ void __launch_bounds__(256)
split_kernel(const float* __restrict__ x, __nv_bfloat16* __restrict__ hi,
             __nv_bfloat16* __restrict__ lo, long long n4)
{
    long long i = ((long long)blockIdx.x * 256 + threadIdx.x);
    if (i >= n4) return;
    const float4 v = ((const float4*)x)[i];
    __nv_bfloat16 h0 = __float2bfloat16(v.x);
    __nv_bfloat16 h1 = __float2bfloat16(v.y);
    __nv_bfloat16 h2 = __float2bfloat16(v.z);
    __nv_bfloat16 h3 = __float2bfloat16(v.w);
    __nv_bfloat162 hh0; hh0.x = h0; hh0.y = h1;
    __nv_bfloat162 hh1; hh1.x = h2; hh1.y = h3;
    __nv_bfloat162 ll0;
    ll0.x = __float2bfloat16(v.x - __bfloat162float(h0));
    ll0.y = __float2bfloat16(v.y - __bfloat162float(h1));
    __nv_bfloat162 ll1;
    ll1.x = __float2bfloat16(v.z - __bfloat162float(h2));
    ll1.y = __float2bfloat16(v.w - __bfloat162float(h3));
    ((__nv_bfloat162*)hi)[i * 2 + 0] = hh0;
    ((__nv_bfloat162*)hi)[i * 2 + 1] = hh1;
    ((__nv_bfloat162*)lo)[i * 2 + 0] = ll0;
    ((__nv_bfloat162*)lo)[i * 2 + 1] = ll1;
}

// W[K][N] fp32 -> T[N][K] bf16 hi/lo
__global__ void __launch_bounds__(256)
transpose_split(const float* __restrict__ W, __nv_bfloat16* __restrict__ Th,
                __nv_bfloat16* __restrict__ Tl, int K, int N)
{
    __shared__ float t[32][33];
    const int n0 = blockIdx.x * 32, k0 = blockIdx.y * 32;
    const int tx = threadIdx.x, ty = threadIdx.y;  // (32, 8)
    #pragma unroll
    for (int p = 0; p < 4; p++) {
        const int kk = ty + p * 8;
        t[kk][tx] = W[(size_t)(k0 + kk) * N + n0 + tx];
    }
    __syncthreads();
    #pragma unroll
    for (int p = 0; p < 4; p++) {
        const int nn = ty + p * 8;
        const float v = t[tx][nn];
        const __nv_bfloat16 h = __float2bfloat16(v);
        Th[(size_t)(n0 + nn) * K + k0 + tx] = h;
        Tl[(size_t)(n0 + nn) * K + k0 + tx] = __float2bfloat16(v - __bfloat162float(h));
    }
}

// ===================== mma.sync split-bf16 GEMM ============================
// MODE 0: C = fp32 (+bias). MODE 1: write bf16 hi/lo split of (acc+bias).
#define RS 80
#define TILE_B   (128 * RS)
#define STAGE_B  (4 * TILE_B)
#define GEMM_SMEM (2 * STAGE_B)      // 81920

template<int MODE>
__global__ void __launch_bounds__(256, 2)
gemm_mma(const __nv_bfloat16* __restrict__ Ah, const __nv_bfloat16* __restrict__ Al,
         const __nv_bfloat16* __restrict__ Bh, const __nv_bfloat16* __restrict__ Bl,
         const float* __restrict__ bias, float* __restrict__ C,
         __nv_bfloat16* __restrict__ Ch, __nv_bfloat16* __restrict__ Cl,
         int Ntot, int K)
{
    extern __shared__ char dsm[];
    const uint32_t sb0 = smem_u32(dsm);
    const int tid  = threadIdx.x;
    const int lane = tid & 31;
    const int wid  = tid >> 5;
    const int wm   = wid & 3;
    const int wn   = wid >> 2;
    const int m0   = blockIdx.y * 128;
    const int n0   = blockIdx.x * 128;

    const size_t Kb = (size_t)K * 2;
    const int NK = K >> 5;

    const char* pAh = (const char*)Ah + (size_t)m0 * Kb;
    const char* pAl = (const char*)Al + (size_t)m0 * Kb;
    const char* pBh = (const char*)Bh + (size_t)n0 * Kb;
    const char* pBl = (const char*)Bl + (size_t)n0 * Kb;

    auto load_stage = [&](int kt, int s) {
        const uint32_t sb = sb0 + (uint32_t)s * STAGE_B;
        const size_t kb = (size_t)kt * 64;
        #pragma unroll
        for (int i = 0; i < 2; i++) {
            const int c   = tid + i * 256;
            const int row = c >> 2;
            const int seg = (c & 3) * 16;
            const uint32_t so = (uint32_t)(row * RS + seg);
            const size_t go = (size_t)row * Kb + kb + seg;
            cp16(sb + so,              pAh + go);
            cp16(sb + TILE_B + so,     pAl + go);
            cp16(sb + 2 * TILE_B + so, pBh + go);
            cp16(sb + 3 * TILE_B + so, pBl + go);
        }
    };

    const uint32_t aRow  = (uint32_t)(wm * 32 + (lane & 15));
    const uint32_t aByte = (uint32_t)((lane >> 4) * 16);
    const uint32_t bRow  = (uint32_t)(wn * 64 + (lane & 7) + ((lane >> 4) & 1) * 8);
    const uint32_t bByte = (uint32_t)(((lane >> 3) & 1) * 16);

    float acc[2][8][4] = {};

    load_stage(0, 0); CP_COMMIT();

    for (int kt = 0; kt < NK; kt++) {
        const int s = kt & 1;
        CP_WAIT0();
        __syncthreads();
        if (kt + 1 < NK) { load_stage(kt + 1, s ^ 1); CP_COMMIT(); }

        const uint32_t sb = sb0 + (uint32_t)s * STAGE_B;

        #pragma unroll
        for (int kk = 0; kk < 2; kk++) {
            uint32_t ah[2][4], al[2][4];
            #pragma unroll
            for (int mi = 0; mi < 2; mi++) {
                const uint32_t ad = sb + (aRow + mi * 16) * RS + kk * 32 + aByte;
                LDSM4(ah[mi][0], ah[mi][1], ah[mi][2], ah[mi][3], ad);
                LDSM4(al[mi][0], al[mi][1], al[mi][2], al[mi][3], ad + TILE_B);
            }
            #pragma unroll
            for (int half = 0; half < 2; half++) {
                uint32_t bh[4][2], bl[4][2];
                #pragma unroll
                for (int p = 0; p < 2; p++) {
                    const uint32_t bd = sb + 2 * TILE_B +
                        (bRow + (half * 2 + p) * 16) * RS + kk * 32 + bByte;
                    uint32_t t0, t1, t2, t3;
                    LDSM4(t0, t1, t2, t3, bd);
                    bh[2 * p][0] = t0; bh[2 * p][1] = t1;
                    bh[2 * p + 1][0] = t2; bh[2 * p + 1][1] = t3;
                    LDSM4(t0, t1, t2, t3, bd + TILE_B);
                    bl[2 * p][0] = t0; bl[2 * p][1] = t1;
                    bl[2 * p + 1][0] = t2; bl[2 * p + 1][1] = t3;
                }
                #pragma unroll
                for (int mi = 0; mi < 2; mi++)
                    #pragma unroll
                    for (int nj = 0; nj < 4; nj++) {
                        float* d = acc[mi][half * 4 + nj];
                        MMA_BF16(d, ah[mi], bh[nj]);
                        MMA_BF16(d, ah[mi], bl[nj]);
                        MMA_BF16(d, al[mi], bh[nj]);
                    }
            }
        }
    }

    const int trow = lane >> 2;
    const int tc   = (lane & 3) * 2;
    #pragma unroll
    for (int mi = 0; mi < 2; mi++) {
        const int r = m0 + wm * 32 + mi * 16 + trow;
        #pragma unroll
        for (int ni = 0; ni < 8; ni++) {
            const int col = n0 + wn * 64 + ni * 8 + tc;
            const float2 bv = *(const float2*)(bias + col);
            const float v00 = acc[mi][ni][0] + bv.x;
            const float v01 = acc[mi][ni][1] + bv.y;
            const float v10 = acc[mi][ni][2] + bv.x;
            const float v11 = acc[mi][ni][3] + bv.y;
            if (MODE == 0) {
                float2 o0 = {v00, v01}, o1 = {v10, v11};
                *(float2*)(C + (size_t)r * Ntot + col) = o0;
                *(float2*)(C + (size_t)(r + 8) * Ntot + col) = o1;
            } else {
                __nv_bfloat16 h00 = __float2bfloat16(v00);
                __nv_bfloat16 h01 = __float2bfloat16(v01);
                __nv_bfloat16 h10 = __float2bfloat16(v10);
                __nv_bfloat16 h11 = __float2bfloat16(v11);
                __nv_bfloat162 ph0; ph0.x = h00; ph0.y = h01;
                __nv_bfloat162 ph1; ph1.x = h10; ph1.y = h11;
                __nv_bfloat162 pl0;
                pl0.x = __float2bfloat16(v00 - __bfloat162float(h00));
                pl0.y = __float2bfloat16(v01 - __bfloat162float(h01));
                __nv_bfloat162 pl1;
                pl1.x = __float2bfloat16(v10 - __bfloat162float(h10));
                pl1.y = __float2bfloat16(v11 - __bfloat162float(h11));
                *(__nv_bfloat162*)(Ch + (size_t)r * Ntot + col) = ph0;
                *(__nv_bfloat162*)(Cl + (size_t)r * Ntot + col) = pl0;
                *(__nv_bfloat162*)(Ch + (size_t)(r + 8) * Ntot + col) = ph1;
                *(__nv_bfloat162*)(Cl + (size_t)(r + 8) * Ntot + col) = pl1;
            }
        }
    }
}

// ===================== scores via mma: q k^T * scale + prev ================
// grid (4, 4, 256): 128x128 tile per block per (b,h). K = 64.
#define RS2 144                       // 64 bf16 = 128B + 16B pad
#define SC_TILE (128 * RS2)           // 18432 per operand
#define SC_SMEM (4 * SC_TILE)         // 73728: Qh | Ql | Kh | Kl

__global__ void __launch_bounds__(256, 2)
scores_tc(const float* __restrict__ prev, const float* __restrict__ scale_p,
          float* __restrict__ scores)
{
    extern __shared__ char dsm[];
    const uint32_t sb = smem_u32(dsm);
    const int tid  = threadIdx.x;
    const int lane = tid & 31;
    const int wid  = tid >> 5;
    const int wm   = wid & 3;
    const int wn   = wid >> 2;
    const int bh = blockIdx.z;
    const int b  = bh >> 4;
    const int h  = bh & 15;
    const int q0 = blockIdx.y * 128;
    const int n0 = blockIdx.x * 128;

    // load Q/K tiles (128 rows x 64 bf16 each, hi+lo)
    const char* pQh = (const char*)g_qh + ((size_t)(b * Sc + q0) * Dc + h * DKc) * 2;
    const char* pQl = (const char*)g_ql + ((size_t)(b * Sc + q0) * Dc + h * DKc) * 2;
    const char* pKh = (const char*)g_kh + ((size_t)(b * Sc + n0) * Dc + h * DKc) * 2;
    const char* pKl = (const char*)g_kl + ((size_t)(b * Sc + n0) * Dc + h * DKc) * 2;
    #pragma unroll
    for (int i = 0; i < 4; i++) {
        const int c   = tid + i * 256;
        const int row = c >> 3;
        const int seg = (c & 7) * 16;
        const uint32_t so = (uint32_t)(row * RS2 + seg);
        const size_t go = (size_t)row * (Dc * 2) + seg;
        cp16(sb + so,               pQh + go);
        cp16(sb + SC_TILE + so,     pQl + go);
        cp16(sb + 2 * SC_TILE + so, pKh + go);
        cp16(sb + 3 * SC_TILE + so, pKl + go);
    }
    CP_COMMIT(); CP_WAIT0();
    __syncthreads();

    const uint32_t aRow  = (uint32_t)(wm * 32 + (lane & 15));
    const uint32_t aByte = (uint32_t)((lane >> 4) * 16);
    const uint32_t bRow  = (uint32_t)(wn * 64 + (lane & 7) + ((lane >> 4) & 1) * 8);
    const uint32_t bByte = (uint32_t)(((lane >> 3) & 1) * 16);

    float acc[2][8][4] = {};

    #pragma unroll
    for (int kk = 0; kk < 4; kk++) {
        uint32_t ah[2][4], al[2][4];
        #pragma unroll
        for (int mi = 0; mi < 2; mi++) {
            const uint32_t ad = sb + (aRow + mi * 16) * RS2 + kk * 32 + aByte;
            LDSM4(ah[mi][0], ah[mi][1], ah[mi][2], ah[mi][3], ad);
            LDSM4(al[mi][0], al[mi][1], al[mi][2], al[mi][3], ad + SC_TILE);
        }
        #pragma unroll
        for (int half = 0; half < 2; half++) {
            uint32_t bhr[4][2], blr[4][2];
            #pragma unroll
            for (int p = 0; p < 2; p++) {
                const uint32_t bd = sb + 2 * SC_TILE +
                    (bRow + (half * 2 + p) * 16) * RS2 + kk * 32 + bByte;
                uint32_t t0, t1, t2, t3;
                LDSM4(t0, t1, t2, t3, bd);
                bhr[2 * p][0] = t0; bhr[2 * p][1] = t1;
                bhr[2 * p + 1][0] = t2; bhr[2 * p + 1][1] = t3;
                LDSM4(t0, t1, t2, t3, bd + SC_TILE);
                blr[2 * p][0] = t0; blr[2 * p][1] = t1;
                blr[2 * p + 1][0] = t2; blr[2 * p + 1][1] = t3;
            }
            #pragma unroll
            for (int mi = 0; mi < 2; mi++)
                #pragma unroll
                for (int nj = 0; nj < 4; nj++) {
                    float* d = acc[mi][half * 4 + nj];
                    MMA_BF16(d, ah[mi], bhr[nj]);
                    MMA_BF16(d, ah[mi], blr[nj]);
                    MMA_BF16(d, al[mi], bhr[nj]);
                }
        }
    }

    const float scale = *scale_p;
    const int trow = lane >> 2;
    const int tc   = (lane & 3) * 2;
    const size_t base = ((size_t)(b * Hc + h) * Sc) * Sc;
    #pragma unroll
    for (int mi = 0; mi < 2; mi++) {
        const int r = q0 + wm * 32 + mi * 16 + trow;
        #pragma unroll
        for (int ni = 0; ni < 8; ni++) {
            const int col = n0 + wn * 64 + ni * 8 + tc;
            const size_t o0 = base + (size_t)r * Sc + col;
            const size_t o1 = base + (size_t)(r + 8) * Sc + col;
            const float2 p0 = *(const float2*)(prev + o0);
            const float2 p1 = *(const float2*)(prev + o1);
            float2 w0, w1;
            w0.x = fmaf(acc[mi][ni][0], scale, p0.x);
            w0.y = fmaf(acc[mi][ni][1], scale, p0.y);
            w1.x = fmaf(acc[mi][ni][2], scale, p1.x);
            w1.y = fmaf(acc[mi][ni][3], scale, p1.y);
            *(float2*)(scores + o0) = w0;
            *(float2*)(scores + o1) = w1;
        }
    }
}

// ===================== softmax * gate ======================================
__global__ void __launch_bounds__(256)
softmax_gate_kernel(float* __restrict__ attn, const float* __restrict__ scores)
{
    const int warp = threadIdx.x >> 5;
    const int lane = threadIdx.x & 31;
    const long long row = (long long)blockIdx.x * 8 + warp;

    const float* srow = scores + row * Sc;
    float*       arow = attn   + row * Sc;

    const int b  = (int)(row >> 13);
    const int hq = (int)(row & 8191);
    const int h  = hq >> 9;
    const int q  = hq & 511;
    const float* grow = g_gt + (size_t)(b * Sc + q) * Gc + (size_t)h * Sc;

    float4 x[4];
    float mx = -3.402823466e38f;
    #pragma unroll
    for (int t = 0; t < 4; t++) {
        x[t] = *(const float4*)(srow + t * 128 + lane * 4);
        mx = fmaxf(mx, fmaxf(fmaxf(x[t].x, x[t].y), fmaxf(x[t].z, x[t].w)));
    }
    #pragma unroll
    for (int o = 16; o > 0; o >>= 1)
        mx = fmaxf(mx, __shfl_xor_sync(0xffffffffu, mx, o));

    float sum = 0.0f;
    #pragma unroll
    for (int t = 0; t < 4; t++) {
        x[t].x = __expf(x[t].x - mx);
        x[t].y = __expf(x[t].y - mx);
        x[t].z = __expf(x[t].z - mx);
        x[t].w = __expf(x[t].w - mx);
        sum += (x[t].x + x[t].y) + (x[t].z + x[t].w);
    }
    #pragma unroll
    for (int o = 16; o > 0; o >>= 1)
        sum += __shfl_xor_sync(0xffffffffu, sum, o);
    const float inv = 1.0f / sum;

    #pragma unroll
    for (int t = 0; t < 4; t++) {
        const float4 gv = *(const float4*)(grow + t * 128 + lane * 4);
        float4 o;
        o.x = gv.x * x[t].x * inv;
        o.y = gv.y * x[t].y * inv;
        o.z = gv.z * x[t].z * inv;
        o.w = gv.w * x[t].w * inv;
        *(float4*)(arow + t * 128 + lane * 4) = o;
    }
}

// ===================== ctx = attn @ v via mma ==============================
// grid (4, 256): M-tile 128 per (b,h). N = 64, K loop 512 in chunks of 64.
// attn fp32 converted to bf16 hi/lo in-kernel; v via ldmatrix.trans.
// smem: Ah 128xRS2 | Al 128xRS2 | Vh 64xRS2 | Vl 64xRS2
#define CT_A    (128 * RS2)
#define CT_V    (64 * RS2)
#define CT_SMEM (2 * CT_A + 2 * CT_V)   // 55296

__global__ void __launch_bounds__(256, 2)
ctx_tc(const float* __restrict__ attn,
       __nv_bfloat16* __restrict__ Ch, __nv_bfloat16* __restrict__ Cl)
{
    extern __shared__ char dsm[];
    const uint32_t sA = smem_u32(dsm);
    const uint32_t sV = sA + 2 * CT_A;
    const int tid  = threadIdx.x;
    const int lane = tid & 31;
    const int wid  = tid >> 5;
    const int wm   = wid & 3;      // 4 warps M (32 rows)
    const int wn   = wid >> 2;     // 2 warps N (32 cols)
    const int bh = blockIdx.y;
    const int b  = bh >> 4;
    const int h  = bh & 15;
    const int q0 = blockIdx.x * 128;

    const size_t abase = ((size_t)(b * Hc + h) * Sc + q0) * Sc;
    const char* pVh = (const char*)g_vh + ((size_t)(b * Sc) * Dc + h * DKc) * 2;
    const char* pVl = (const char*)g_vl + ((size_t)(b * Sc) * Dc + h * DKc) * 2;

    const uint32_t aRow  = (uint32_t)(wm * 32 + (lane & 15));
    const uint32_t aByte = (uint32_t)((lane >> 4) * 16);
    // trans B: row = k (lane&15), col byte = (n_off + (lane>>4)*8)*2
    const uint32_t vRowL = (uint32_t)(lane & 15);
    const uint32_t vColB = (uint32_t)((wn * 32 + (lane >> 4) * 8) * 2);

    float acc[2][4][4] = {};

    for (int kt = 0; kt < 8; kt++) {
        __syncthreads();   // protect smem reuse from previous iteration's reads
        // V tile: 64 rows(k) x 64 cols, hi+lo, cp.async
        #pragma unroll
        for (int i = 0; i < 2; i++) {
            const int c   = tid + i * 256;
            const int row = c >> 3;
            const int seg = (c & 7) * 16;
            const uint32_t so = (uint32_t)(row * RS2 + seg);
            const size_t go = (size_t)(kt * 64 + row) * (Dc * 2) + seg;
            cp16(sV + so,        pVh + go);
            cp16(sV + CT_V + so, pVl + go);
        }
        CP_COMMIT();
        // attn tile: 128 rows x 64 fp32 -> bf16 hi/lo in smem
        #pragma unroll
        for (int i = 0; i < 8; i++) {
            const int c   = tid + i * 256;
            const int row = c >> 4;
            const int f4  = c & 15;
            const float4 v = *(const float4*)(attn + abase + (size_t)row * Sc + kt * 64 + f4 * 4);
            __nv_bfloat16 h0 = __float2bfloat16(v.x);
            __nv_bfloat16 h1 = __float2bfloat16(v.y);
            __nv_bfloat16 h2 = __float2bfloat16(v.z);
            __nv_bfloat16 h3 = __float2bfloat16(v.w);
            __nv_bfloat162 ph0; ph0.x = h0; ph0.y = h1;
            __nv_bfloat162 ph1; ph1.x = h2; ph1.y = h3;
            __nv_bfloat162 pl0;
            pl0.x = __float2bfloat16(v.x - __bfloat162float(h0));
            pl0.y = __float2bfloat16(v.y - __bfloat162float(h1));
            __nv_bfloat162 pl1;
            pl1.x = __float2bfloat16(v.z - __bfloat162float(h2));
            pl1.y = __float2bfloat16(v.w - __bfloat162float(h3));
            const uint32_t so = (uint32_t)(row * RS2 + f4 * 8);
            *(uint32_t*)(dsm + (so))              = *(uint32_t*)&ph0;
            *(uint32_t*)(dsm + (so + 4))          = *(uint32_t*)&ph1;
            *(uint32_t*)(dsm + (CT_A + so))       = *(uint32_t*)&pl0;
            *(uint32_t*)(dsm + (CT_A + so + 4))   = *(uint32_t*)&pl1;
        }
        CP_WAIT0();
        __syncthreads();

        #pragma unroll
        for (int kk = 0; kk < 4; kk++) {
            uint32_t ah[2][4], al[2][4];
            #pragma unroll
            for (int mi = 0; mi < 2; mi++) {
                const uint32_t ad = sA + (aRow + mi * 16) * RS2 + kk * 32 + aByte;
                LDSM4(ah[mi][0], ah[mi][1], ah[mi][2], ah[mi][3], ad);
                LDSM4(al[mi][0], al[mi][1], al[mi][2], al[mi][3], ad + CT_A);
            }
            uint32_t bh_[4][2], bl_[4][2];
            #pragma unroll
            for (int p = 0; p < 2; p++) {
                const uint32_t vd = sV + (kk * 16 + vRowL) * RS2 + vColB + p * 32;
                uint32_t t0, t1, t2, t3;
                LDSM4T(t0, t1, t2, t3, vd);
                bh_[2 * p][0] = t0; bh_[2 * p][1] = t1;
                bh_[2 * p + 1][0] = t2; bh_[2 * p + 1][1] = t3;
                LDSM4T(t0, t1, t2, t3, vd + CT_V);
                bl_[2 * p][0] = t0; bl_[2 * p][1] = t1;
                bl_[2 * p + 1][0] = t2; bl_[2 * p + 1][1] = t3;
            }
            #pragma unroll
            for (int mi = 0; mi < 2; mi++)
                #pragma unroll
                for (int nj = 0; nj < 4; nj++) {
                    float* d = acc[mi][nj];
                    MMA_BF16(d, ah[mi], bh_[nj]);
                    MMA_BF16(d, ah[mi], bl_[nj]);
                    MMA_BF16(d, al[mi], bh_[nj]);
                }
        }
    }

    // epilogue: ctx bf16 hi/lo at [(b*S+q), h*64 + col] (row stride Dc)
    const int trow = lane >> 2;
    const int tc   = (lane & 3) * 2;
    #pragma unroll
    for (int mi = 0; mi < 2; mi++) {
        const int r = b * Sc + q0 + wm * 32 + mi * 16 + trow;
        #pragma unroll
        for (int nj = 0; nj < 4; nj++) {
            const int col = h * DKc + wn * 32 + nj * 8 + tc;
            const float v00 = acc[mi][nj][0], v01 = acc[mi][nj][1];
            const float v10 = acc[mi][nj][2], v11 = acc[mi][nj][3];
            __nv_bfloat16 h00 = __float2bfloat16(v00);
            __nv_bfloat16 h01 = __float2bfloat16(v01);
            __nv_bfloat16 h10 = __float2bfloat16(v10);
            __nv_bfloat16 h11 = __float2bfloat16(v11);
            __nv_bfloat162 ph0; ph0.x = h00; ph0.y = h01;
            __nv_bfloat162 ph1; ph1.x = h10; ph1.y = h11;
            __nv_bfloat162 pl0;
            pl0.x = __float2bfloat16(v00 - __bfloat162float(h00));
            pl0.y = __float2bfloat16(v01 - __bfloat162float(h01));
            __nv_bfloat162 pl1;
            pl1.x = __float2bfloat16(v10 - __bfloat162float(h10));
            pl1.y = __float2bfloat16(v11 - __bfloat162float(h11));
            *(__nv_bfloat162*)(Ch + (size_t)r * Dc + col) = ph0;
            *(__nv_bfloat162*)(Cl + (size_t)r * Dc + col) = pl0;
            *(__nv_bfloat162*)(Ch + (size_t)(r + 8) * Dc + col) = ph1;
            *(__nv_bfloat162*)(Cl + (size_t)(r + 8) * Dc + col) = pl1;
        }
    }
}

// ---------------------------------------------------------------------------
extern "C" void kernel_launch(void* const* d_in, const int* in_sizes, int n_in,
                              void* d_out, int out_size)
{
    (void)in_sizes; (void)n_in; (void)out_size;

    const float* Q     = (const float*)d_in[0];
    const float* prev  = (const float*)d_in[1];
    const float* Wq    = (const float*)d_in[2];
    const float* bq    = (const float*)d_in[3];
    const float* Wk    = (const float*)d_in[4];
    const float* bk    = (const float*)d_in[5];
    const float* Wv    = (const float*)d_in[6];
    const float* bv    = (const float*)d_in[7];
    const float* Wg    = (const float*)d_in[8];
    const float* bg    = (const float*)d_in[9];
    const float* Wo    = (const float*)d_in[10];
    const float* bo    = (const float*)d_in[11];
    const float* scale = (const float*)d_in[12];

    float* out    = (float*)d_out;
    float* attn   = out + OUT_ELEMS;
    float* scores = attn + ATTN_ELEMS;

    float* gb;
    __nv_bfloat16 *ah, *al, *wh, *wl, *qh, *ql, *kh, *kl, *vh, *vl;
    cudaGetSymbolAddress((void**)&gb, g_gt);
    cudaGetSymbolAddress((void**)&ah, g_ah);
    cudaGetSymbolAddress((void**)&al, g_al);
    cudaGetSymbolAddress((void**)&wh, g_wh);
    cudaGetSymbolAddress((void**)&wl, g_wl);
    cudaGetSymbolAddress((void**)&qh, g_qh);
    cudaGetSymbolAddress((void**)&ql, g_ql);
    cudaGetSymbolAddress((void**)&kh, g_kh);
    cudaGetSymbolAddress((void**)&kl, g_kl);
    cudaGetSymbolAddress((void**)&vh, g_vh);
    cudaGetSymbolAddress((void**)&vl, g_vl);

    cudaFuncSetAttribute(gemm_mma<0>, cudaFuncAttributeMaxDynamicSharedMemorySize, GEMM_SMEM);
    cudaFuncSetAttribute(gemm_mma<1>, cudaFuncAttributeMaxDynamicSharedMemorySize, GEMM_SMEM);
    cudaFuncSetAttribute(scores_tc,   cudaFuncAttributeMaxDynamicSharedMemorySize, SC_SMEM);
    cudaFuncSetAttribute(ctx_tc,      cudaFuncAttributeMaxDynamicSharedMemorySize, CT_SMEM);

    const dim3 tblk(32, 8);
    const long long nQ4 = (long long)Mc * Dc / 4;

    // split input activations into bf16 hi/lo
    split_kernel<<<(int)(nQ4 / 256), 256>>>(Q, ah, al, nQ4);

    // q/k/v projections -> bf16 hi/lo directly
    transpose_split<<<dim3(Dc / 32, Dc / 32), tblk>>>(Wq, wh, wl, Dc, Dc);
    gemm_mma<1><<<dim3(Dc / 128, Mc / 128), 256, GEMM_SMEM>>>(ah, al, wh, wl, bq, nullptr, qh, ql, Dc, Dc);
    transpose_split<<<dim3(Dc / 32, Dc / 32), tblk>>>(Wk, wh, wl, Dc, Dc);
    gemm_mma<1><<<dim3(Dc / 128, Mc / 128), 256, GEMM_SMEM>>>(ah, al, wh, wl, bk, nullptr, kh, kl, Dc, Dc);
    transpose_split<<<dim3(Dc / 32, Dc / 32), tblk>>>(Wv, wh, wl, Dc, Dc);
    gemm_mma<1><<<dim3(Dc / 128, Mc / 128), 256, GEMM_SMEM>>>(ah, al, wh, wl, bv, nullptr, vh, vl, Dc, Dc);
    // gate projection (N = 8192) -> fp32
    transpose_split<<<dim3(Gc / 32, Dc / 32), tblk>>>(Wg, wh, wl, Dc, Gc);
    gemm_mma<0><<<dim3(Gc / 128, Mc / 128), 256, GEMM_SMEM>>>(ah, al, wh, wl, bg, gb, nullptr, nullptr, Gc, Dc);

    // scores = q k^T * scale + prev (tensor cores)
    scores_tc<<<dim3(4, 4, Bc * Hc), 256, SC_SMEM>>>(prev, scale, scores);
    // attn = gate * softmax(scores)
    softmax_gate_kernel<<<(Bc * Hc * Sc) / 8, 256>>>(attn, scores);
    // ctx = attn @ v (tensor cores) -> bf16 hi/lo into ah/al
    ctx_tc<<<dim3(4, Bc * Hc), 256, CT_SMEM>>>(attn, ah, al);

    // out = ctx @ Wo + bo
    transpose_split<<<dim3(Dc / 32, Dc / 32), tblk>>>(Wo, wh, wl, Dc, Dc);
    gemm_mma<0><<<dim3(Dc / 128, Mc / 128), 256, GEMM_SMEM>>>(ah, al, wh, wl, bo, out, nullptr, nullptr, Dc, Dc);
}

// round 8
// speedup vs baseline: 3.1979x; 1.2215x over previous
#include <cuda_runtime.h>
#include <cuda_fp16.h>
#include <cstdint>
#include <cstddef>

// Problem constants
#define Bc  16
#define Sc  512
#define Dc  1024
#define Hc  16
#define DKc 64
#define Mc  8192   // B*S
#define Gc  8192   // H*S

#define OUT_ELEMS  8388608LL
#define ATTN_ELEMS 67108864LL

// -------------------- device scratch (static globals; no allocs) -----------
__device__ float g_gt [(size_t)Mc * Gc];      // gate [b*S+s][h*S+k] fp32
__device__ __half g_ah[(size_t)Mc * Dc];      // activation hi / later ctx hi
__device__ __half g_al[(size_t)Mc * Dc];      // activation lo / later ctx lo
__device__ __half g_wh[(size_t)Gc * Dc];      // weight^T hi [N,K]
__device__ __half g_wl[(size_t)Gc * Dc];      // weight^T lo
__device__ __half g_qh[(size_t)Mc * Dc];
__device__ __half g_ql[(size_t)Mc * Dc];
__device__ __half g_kh[(size_t)Mc * Dc];
__device__ __half g_kl[(size_t)Mc * Dc];
__device__ __half g_vh[(size_t)Mc * Dc];
__device__ __half g_vl[(size_t)Mc * Dc];

// ===================== PTX helpers (sm_80-level only) ======================
__device__ __forceinline__ uint32_t smem_u32(const void* p) {
    uint32_t a;
    asm("{ .reg .u64 t; cvta.to.shared.u64 t, %1; cvt.u32.u64 %0, t; }" : "=r"(a) : "l"(p));
    return a;
}
__device__ __forceinline__ void cp16(uint32_t smem, const void* g) {
    asm volatile("cp.async.cg.shared.global [%0], [%1], 16;\n" :: "r"(smem), "l"(g));
}
#define CP_COMMIT() asm volatile("cp.async.commit_group;" ::: "memory")
#define CP_WAIT0()  asm volatile("cp.async.wait_group 0;" ::: "memory")

#define LDSM4(r0, r1, r2, r3, addr) \
    asm volatile("ldmatrix.sync.aligned.m8n8.x4.shared.b16 {%0,%1,%2,%3}, [%4];" \
        : "=r"(r0), "=r"(r1), "=r"(r2), "=r"(r3) : "r"(addr))
#define LDSM4T(r0, r1, r2, r3, addr) \
    asm volatile("ldmatrix.sync.aligned.m8n8.x4.trans.shared.b16 {%0,%1,%2,%3}, [%4];" \
        : "=r"(r0), "=r"(r1), "=r"(r2), "=r"(r3) : "r"(addr))

#define MMA_F16(d, a, b) \
    asm volatile("mma.sync.aligned.m16n8k16.row.col.f32.f16.f16.f32 " \
        "{%0,%1,%2,%3},{%4,%5,%6,%7},{%8,%9},{%0,%1,%2,%3};" \
        : "+f"((d)[0]), "+f"((d)[1]), "+f"((d)[2]), "+f"((d)[3]) \
        : "r"((a)[0]), "r"((a)[1]), "r"((a)[2]), "r"((a)[3]), \
          "r"((b)[0]), "r"((b)[1]))

// ===================== conversion kernels ==================================
__global__ void __launch_bounds__(256)
split_kernel(const float* __restrict__ x, __half* __restrict__ hi,
             __half* __restrict__ lo, long long n4)
{
    long long i = ((long long)blockIdx.x * 256 + threadIdx.x);
    if (i >= n4) return;
    const float4 v = ((const float4*)x)[i];
    const __half h0 = __float2half_rn(v.x);
    const __half h1 = __float2half_rn(v.y);
    const __half h2 = __float2half_rn(v.z);
    const __half h3 = __float2half_rn(v.w);
    ((__half2*)hi)[i * 2 + 0] = __halves2half2(h0, h1);
    ((__half2*)hi)[i * 2 + 1] = __halves2half2(h2, h3);
    ((__half2*)lo)[i * 2 + 0] = __halves2half2(
        __float2half_rn(v.x - __half2float(h0)),
        __float2half_rn(v.y - __half2float(h1)));
    ((__half2*)lo)[i * 2 + 1] = __halves2half2(
        __float2half_rn(v.z - __half2float(h2)),
        __float2half_rn(v.w - __half2float(h3)));
}

// W[K][N] fp32 -> T[N][K] fp16 hi/lo
__global__ void __launch_bounds__(256)
transpose_split(const float* __restrict__ W, __half* __restrict__ Th,
                __half* __restrict__ Tl, int K, int N)
{
    __shared__ float t[32][33];
    const int n0 = blockIdx.x * 32, k0 = blockIdx.y * 32;
    const int tx = threadIdx.x, ty = threadIdx.y;  // (32, 8)
    #pragma unroll
    for (int p = 0; p < 4; p++) {
        const int kk = ty + p * 8;
        t[kk][tx] = W[(size_t)(k0 + kk) * N + n0 + tx];
    }
    __syncthreads();
    #pragma unroll
    for (int p = 0; p < 4; p++) {
        const int nn = ty + p * 8;
        const float v = t[tx][nn];
        const __half h = __float2half_rn(v);
        Th[(size_t)(n0 + nn) * K + k0 + tx] = h;
        Tl[(size_t)(n0 + nn) * K + k0 + tx] = __float2half_rn(v - __half2float(h));
    }
}

// ===================== mma.sync split-fp16 GEMM ============================
// PASSES==3: C = Ah@Bh + Ah@Bl + Al@Bh.  PASSES==2: C = Ah@Bh + Al@Bh.
// MODE 0: C fp32 (+bias). MODE 1: write fp16 hi/lo split of (acc+bias).
#define RS 80
#define TILE_B   (128 * RS)
#define STAGE_B  (4 * TILE_B)
#define GEMM_SMEM (2 * STAGE_B)      // 81920

template<int MODE, int PASSES>
__global__ void __launch_bounds__(256, 2)
gemm_mma(const __half* __restrict__ Ah, const __half* __restrict__ Al,
         const __half* __restrict__ Bh, const __half* __restrict__ Bl,
         const float* __restrict__ bias, float* __restrict__ C,
         __half* __restrict__ Ch, __half* __restrict__ Cl,
         int Ntot, int K)
{
    extern __shared__ char dsm[];
    const uint32_t sb0 = smem_u32(dsm);
    const int tid  = threadIdx.x;
    const int lane = tid & 31;
    const int wid  = tid >> 5;
    const int wm   = wid & 3;
    const int wn   = wid >> 2;
    const int m0   = blockIdx.y * 128;
    const int n0   = blockIdx.x * 128;

    const size_t Kb = (size_t)K * 2;
    const int NK = K >> 5;

    const char* pAh = (const char*)Ah + (size_t)m0 * Kb;
    const char* pAl = (const char*)Al + (size_t)m0 * Kb;
    const char* pBh = (const char*)Bh + (size_t)n0 * Kb;
    const char* pBl = (const char*)Bl + (size_t)n0 * Kb;

    auto load_stage = [&](int kt, int s) {
        const uint32_t sb = sb0 + (uint32_t)s * STAGE_B;
        const size_t kb = (size_t)kt * 64;
        #pragma unroll
        for (int i = 0; i < 2; i++) {
            const int c   = tid + i * 256;
            const int row = c >> 2;
            const int seg = (c & 3) * 16;
            const uint32_t so = (uint32_t)(row * RS + seg);
            const size_t go = (size_t)row * Kb + kb + seg;
            cp16(sb + so,              pAh + go);
            cp16(sb + TILE_B + so,     pAl + go);
            cp16(sb + 2 * TILE_B + so, pBh + go);
            if (PASSES == 3) cp16(sb + 3 * TILE_B + so, pBl + go);
        }
    };

    const uint32_t aRow  = (uint32_t)(wm * 32 + (lane & 15));
    const uint32_t aByte = (uint32_t)((lane >> 4) * 16);
    const uint32_t bRow  = (uint32_t)(wn * 64 + (lane & 7) + ((lane >> 4) & 1) * 8);
    const uint32_t bByte = (uint32_t)(((lane >> 3) & 1) * 16);

    float acc[2][8][4] = {};

    load_stage(0, 0); CP_COMMIT();

    for (int kt = 0; kt < NK; kt++) {
        const int s = kt & 1;
        CP_WAIT0();
        __syncthreads();
        if (kt + 1 < NK) { load_stage(kt + 1, s ^ 1); CP_COMMIT(); }

        const uint32_t sb = sb0 + (uint32_t)s * STAGE_B;

        #pragma unroll
        for (int kk = 0; kk < 2; kk++) {
            uint32_t ah[2][4], al[2][4];
            #pragma unroll
            for (int mi = 0; mi < 2; mi++) {
                const uint32_t ad = sb + (aRow + mi * 16) * RS + kk * 32 + aByte;
                LDSM4(ah[mi][0], ah[mi][1], ah[mi][2], ah[mi][3], ad);
                LDSM4(al[mi][0], al[mi][1], al[mi][2], al[mi][3], ad + TILE_B);
            }
            #pragma unroll
            for (int hf = 0; hf < 2; hf++) {
                uint32_t bh[4][2], bl[4][2];
                #pragma unroll
                for (int p = 0; p < 2; p++) {
                    const uint32_t bd = sb + 2 * TILE_B +
                        (bRow + (hf * 2 + p) * 16) * RS + kk * 32 + bByte;
                    uint32_t t0, t1, t2, t3;
                    LDSM4(t0, t1, t2, t3, bd);
                    bh[2 * p][0] = t0; bh[2 * p][1] = t1;
                    bh[2 * p + 1][0] = t2; bh[2 * p + 1][1] = t3;
                    if (PASSES == 3) {
                        LDSM4(t0, t1, t2, t3, bd + TILE_B);
                        bl[2 * p][0] = t0; bl[2 * p][1] = t1;
                        bl[2 * p + 1][0] = t2; bl[2 * p + 1][1] = t3;
                    }
                }
                #pragma unroll
                for (int mi = 0; mi < 2; mi++)
                    #pragma unroll
                    for (int nj = 0; nj < 4; nj++) {
                        float* d = acc[mi][hf * 4 + nj];
                        MMA_F16(d, ah[mi], bh[nj]);
                        if (PASSES == 3) MMA_F16(d, ah[mi], bl[nj]);
                        MMA_F16(d, al[mi], bh[nj]);
                    }
            }
        }
    }

    const int trow = lane >> 2;
    const int tc   = (lane & 3) * 2;
    #pragma unroll
    for (int mi = 0; mi < 2; mi++) {
        const int r = m0 + wm * 32 + mi * 16 + trow;
        #pragma unroll
        for (int ni = 0; ni < 8; ni++) {
            const int col = n0 + wn * 64 + ni * 8 + tc;
            const float2 bv = *(const float2*)(bias + col);
            const float v00 = acc[mi][ni][0] + bv.x;
            const float v01 = acc[mi][ni][1] + bv.y;
            const float v10 = acc[mi][ni][2] + bv.x;
            const float v11 = acc[mi][ni][3] + bv.y;
            if (MODE == 0) {
                float2 o0 = {v00, v01}, o1 = {v10, v11};
                *(float2*)(C + (size_t)r * Ntot + col) = o0;
                *(float2*)(C + (size_t)(r + 8) * Ntot + col) = o1;
            } else {
                const __half h00 = __float2half_rn(v00);
                const __half h01 = __float2half_rn(v01);
                const __half h10 = __float2half_rn(v10);
                const __half h11 = __float2half_rn(v11);
                *(__half2*)(Ch + (size_t)r * Ntot + col) = __halves2half2(h00, h01);
                *(__half2*)(Cl + (size_t)r * Ntot + col) = __halves2half2(
                    __float2half_rn(v00 - __half2float(h00)),
                    __float2half_rn(v01 - __half2float(h01)));
                *(__half2*)(Ch + (size_t)(r + 8) * Ntot + col) = __halves2half2(h10, h11);
                *(__half2*)(Cl + (size_t)(r + 8) * Ntot + col) = __halves2half2(
                    __float2half_rn(v10 - __half2float(h10)),
                    __float2half_rn(v11 - __half2float(h11)));
            }
        }
    }
}

// ===================== scores via mma: q k^T * scale + prev ================
// grid (4, 4, 256): 128x128 tile per block per (b,h). K = 64. 3-pass.
#define RS2 144
#define SC_TILE (128 * RS2)
#define SC_SMEM (4 * SC_TILE)         // 73728: Qh | Ql | Kh | Kl

__global__ void __launch_bounds__(256, 2)
scores_tc(const float* __restrict__ prev, const float* __restrict__ scale_p,
          float* __restrict__ scores)
{
    extern __shared__ char dsm[];
    const uint32_t sb = smem_u32(dsm);
    const int tid  = threadIdx.x;
    const int lane = tid & 31;
    const int wid  = tid >> 5;
    const int wm   = wid & 3;
    const int wn   = wid >> 2;
    const int bh = blockIdx.z;
    const int b  = bh >> 4;
    const int h  = bh & 15;
    const int q0 = blockIdx.y * 128;
    const int n0 = blockIdx.x * 128;

    const char* pQh = (const char*)g_qh + ((size_t)(b * Sc + q0) * Dc + h * DKc) * 2;
    const char* pQl = (const char*)g_ql + ((size_t)(b * Sc + q0) * Dc + h * DKc) * 2;
    const char* pKh = (const char*)g_kh + ((size_t)(b * Sc + n0) * Dc + h * DKc) * 2;
    const char* pKl = (const char*)g_kl + ((size_t)(b * Sc + n0) * Dc + h * DKc) * 2;
    #pragma unroll
    for (int i = 0; i < 4; i++) {
        const int c   = tid + i * 256;
        const int row = c >> 3;
        const int seg = (c & 7) * 16;
        const uint32_t so = (uint32_t)(row * RS2 + seg);
        const size_t go = (size_t)row * (Dc * 2) + seg;
        cp16(sb + so,               pQh + go);
        cp16(sb + SC_TILE + so,     pQl + go);
        cp16(sb + 2 * SC_TILE + so, pKh + go);
        cp16(sb + 3 * SC_TILE + so, pKl + go);
    }
    CP_COMMIT(); CP_WAIT0();
    __syncthreads();

    const uint32_t aRow  = (uint32_t)(wm * 32 + (lane & 15));
    const uint32_t aByte = (uint32_t)((lane >> 4) * 16);
    const uint32_t bRow  = (uint32_t)(wn * 64 + (lane & 7) + ((lane >> 4) & 1) * 8);
    const uint32_t bByte = (uint32_t)(((lane >> 3) & 1) * 16);

    float acc[2][8][4] = {};

    #pragma unroll
    for (int kk = 0; kk < 4; kk++) {
        uint32_t ah[2][4], al[2][4];
        #pragma unroll
        for (int mi = 0; mi < 2; mi++) {
            const uint32_t ad = sb + (aRow + mi * 16) * RS2 + kk * 32 + aByte;
            LDSM4(ah[mi][0], ah[mi][1], ah[mi][2], ah[mi][3], ad);
            LDSM4(al[mi][0], al[mi][1], al[mi][2], al[mi][3], ad + SC_TILE);
        }
        #pragma unroll
        for (int hf = 0; hf < 2; hf++) {
            uint32_t bhr[4][2], blr[4][2];
            #pragma unroll
            for (int p = 0; p < 2; p++) {
                const uint32_t bd = sb + 2 * SC_TILE +
                    (bRow + (hf * 2 + p) * 16) * RS2 + kk * 32 + bByte;
                uint32_t t0, t1, t2, t3;
                LDSM4(t0, t1, t2, t3, bd);
                bhr[2 * p][0] = t0; bhr[2 * p][1] = t1;
                bhr[2 * p + 1][0] = t2; bhr[2 * p + 1][1] = t3;
                LDSM4(t0, t1, t2, t3, bd + SC_TILE);
                blr[2 * p][0] = t0; blr[2 * p][1] = t1;
                blr[2 * p + 1][0] = t2; blr[2 * p + 1][1] = t3;
            }
            #pragma unroll
            for (int mi = 0; mi < 2; mi++)
                #pragma unroll
                for (int nj = 0; nj < 4; nj++) {
                    float* d = acc[mi][hf * 4 + nj];
                    MMA_F16(d, ah[mi], bhr[nj]);
                    MMA_F16(d, ah[mi], blr[nj]);
                    MMA_F16(d, al[mi], bhr[nj]);
                }
        }
    }

    const float scale = *scale_p;
    const int trow = lane >> 2;
    const int tc   = (lane & 3) * 2;
    const size_t base = ((size_t)(b * Hc + h) * Sc) * Sc;
    #pragma unroll
    for (int mi = 0; mi < 2; mi++) {
        const int r = q0 + wm * 32 + mi * 16 + trow;
        #pragma unroll
        for (int ni = 0; ni < 8; ni++) {
            const int col = n0 + wn * 64 + ni * 8 + tc;
            const size_t o0 = base + (size_t)r * Sc + col;
            const size_t o1 = base + (size_t)(r + 8) * Sc + col;
            const float2 p0 = *(const float2*)(prev + o0);
            const float2 p1 = *(const float2*)(prev + o1);
            float2 w0, w1;
            w0.x = fmaf(acc[mi][ni][0], scale, p0.x);
            w0.y = fmaf(acc[mi][ni][1], scale, p0.y);
            w1.x = fmaf(acc[mi][ni][2], scale, p1.x);
            w1.y = fmaf(acc[mi][ni][3], scale, p1.y);
            *(float2*)(scores + o0) = w0;
            *(float2*)(scores + o1) = w1;
        }
    }
}

// ===================== softmax * gate ======================================
__global__ void __launch_bounds__(256)
softmax_gate_kernel(float* __restrict__ attn, const float* __restrict__ scores)
{
    const int warp = threadIdx.x >> 5;
    const int lane = threadIdx.x & 31;
    const long long row = (long long)blockIdx.x * 8 + warp;

    const float* srow = scores + row * Sc;
    float*       arow = attn   + row * Sc;

    const int b  = (int)(row >> 13);
    const int hq = (int)(row & 8191);
    const int h  = hq >> 9;
    const int q  = hq & 511;
    const float* grow = g_gt + (size_t)(b * Sc + q) * Gc + (size_t)h * Sc;

    float4 x[4];
    float mx = -3.402823466e38f;
    #pragma unroll
    for (int t = 0; t < 4; t++) {
        x[t] = *(const float4*)(srow + t * 128 + lane * 4);
        mx = fmaxf(mx, fmaxf(fmaxf(x[t].x, x[t].y), fmaxf(x[t].z, x[t].w)));
    }
    #pragma unroll
    for (int o = 16; o > 0; o >>= 1)
        mx = fmaxf(mx, __shfl_xor_sync(0xffffffffu, mx, o));

    float sum = 0.0f;
    #pragma unroll
    for (int t = 0; t < 4; t++) {
        x[t].x = __expf(x[t].x - mx);
        x[t].y = __expf(x[t].y - mx);
        x[t].z = __expf(x[t].z - mx);
        x[t].w = __expf(x[t].w - mx);
        sum += (x[t].x + x[t].y) + (x[t].z + x[t].w);
    }
    #pragma unroll
    for (int o = 16; o > 0; o >>= 1)
        sum += __shfl_xor_sync(0xffffffffu, sum, o);
    const float inv = 1.0f / sum;

    #pragma unroll
    for (int t = 0; t < 4; t++) {
        const float4 gv = *(const float4*)(grow + t * 128 + lane * 4);
        float4 o;
        o.x = gv.x * x[t].x * inv;
        o.y = gv.y * x[t].y * inv;
        o.z = gv.z * x[t].z * inv;
        o.w = gv.w * x[t].w * inv;
        *(float4*)(arow + t * 128 + lane * 4) = o;
    }
}

// ===================== ctx = attn @ v via mma ==============================
#define CT_A    (128 * RS2)
#define CT_V    (64 * RS2)
#define CT_SMEM (2 * CT_A + 2 * CT_V)   // 55296

__global__ void __launch_bounds__(256, 2)
ctx_tc(const float* __restrict__ attn,
       __half* __restrict__ Ch, __half* __restrict__ Cl)
{
    extern __shared__ char dsm[];
    const uint32_t sA = smem_u32(dsm);
    const uint32_t sV = sA + 2 * CT_A;
    const int tid  = threadIdx.x;
    const int lane = tid & 31;
    const int wid  = tid >> 5;
    const int wm   = wid & 3;
    const int wn   = wid >> 2;
    const int bh = blockIdx.y;
    const int b  = bh >> 4;
    const int h  = bh & 15;
    const int q0 = blockIdx.x * 128;

    const size_t abase = ((size_t)(b * Hc + h) * Sc + q0) * Sc;
    const char* pVh = (const char*)g_vh + ((size_t)(b * Sc) * Dc + h * DKc) * 2;
    const char* pVl = (const char*)g_vl + ((size_t)(b * Sc) * Dc + h * DKc) * 2;

    const uint32_t aRow  = (uint32_t)(wm * 32 + (lane & 15));
    const uint32_t aByte = (uint32_t)((lane >> 4) * 16);
    const uint32_t vRowL = (uint32_t)(lane & 15);
    const uint32_t vColB = (uint32_t)((wn * 32 + (lane >> 4) * 8) * 2);

    float acc[2][4][4] = {};

    for (int kt = 0; kt < 8; kt++) {
        __syncthreads();
        #pragma unroll
        for (int i = 0; i < 2; i++) {
            const int c   = tid + i * 256;
            const int row = c >> 3;
            const int seg = (c & 7) * 16;
            const uint32_t so = (uint32_t)(row * RS2 + seg);
            const size_t go = (size_t)(kt * 64 + row) * (Dc * 2) + seg;
            cp16(sV + so,        pVh + go);
            cp16(sV + CT_V + so, pVl + go);
        }
        CP_COMMIT();
        #pragma unroll
        for (int i = 0; i < 8; i++) {
            const int c   = tid + i * 256;
            const int row = c >> 4;
            const int f4  = c & 15;
            const float4 v = *(const float4*)(attn + abase + (size_t)row * Sc + kt * 64 + f4 * 4);
            const __half h0 = __float2half_rn(v.x);
            const __half h1 = __float2half_rn(v.y);
            const __half h2 = __float2half_rn(v.z);
            const __half h3 = __float2half_rn(v.w);
            const __half2 ph0 = __halves2half2(h0, h1);
            const __half2 ph1 = __halves2half2(h2, h3);
            const __half2 pl0 = __halves2half2(
                __float2half_rn(v.x - __half2float(h0)),
                __float2half_rn(v.y - __half2float(h1)));
            const __half2 pl1 = __halves2half2(
                __float2half_rn(v.z - __half2float(h2)),
                __float2half_rn(v.w - __half2float(h3)));
            const uint32_t so = (uint32_t)(row * RS2 + f4 * 8);
            *(uint32_t*)(dsm + (so))            = *(uint32_t*)&ph0;
            *(uint32_t*)(dsm + (so + 4))        = *(uint32_t*)&ph1;
            *(uint32_t*)(dsm + (CT_A + so))     = *(uint32_t*)&pl0;
            *(uint32_t*)(dsm + (CT_A + so + 4)) = *(uint32_t*)&pl1;
        }
        CP_WAIT0();
        __syncthreads();

        #pragma unroll
        for (int kk = 0; kk < 4; kk++) {
            uint32_t ah[2][4], al[2][4];
            #pragma unroll
            for (int mi = 0; mi < 2; mi++) {
                const uint32_t ad = sA + (aRow + mi * 16) * RS2 + kk * 32 + aByte;
                LDSM4(ah[mi][0], ah[mi][1], ah[mi][2], ah[mi][3], ad);
                LDSM4(al[mi][0], al[mi][1], al[mi][2], al[mi][3], ad + CT_A);
            }
            uint32_t bh_[4][2], bl_[4][2];
            #pragma unroll
            for (int p = 0; p < 2; p++) {
                const uint32_t vd = sV + (kk * 16 + vRowL) * RS2 + vColB + p * 32;
                uint32_t t0, t1, t2, t3;
                LDSM4T(t0, t1, t2, t3, vd);
                bh_[2 * p][0] = t0; bh_[2 * p][1] = t1;
                bh_[2 * p + 1][0] = t2; bh_[2 * p + 1][1] = t3;
                LDSM4T(t0, t1, t2, t3, vd + CT_V);
                bl_[2 * p][0] = t0; bl_[2 * p][1] = t1;
                bl_[2 * p + 1][0] = t2; bl_[2 * p + 1][1] = t3;
            }
            #pragma unroll
            for (int mi = 0; mi < 2; mi++)
                #pragma unroll
                for (int nj = 0; nj < 4; nj++) {
                    float* d = acc[mi][nj];
                    MMA_F16(d, ah[mi], bh_[nj]);
                    MMA_F16(d, ah[mi], bl_[nj]);
                    MMA_F16(d, al[mi], bh_[nj]);
                }
        }
    }

    const int trow = lane >> 2;
    const int tc   = (lane & 3) * 2;
    #pragma unroll
    for (int mi = 0; mi < 2; mi++) {
        const int r = b * Sc + q0 + wm * 32 + mi * 16 + trow;
        #pragma unroll
        for (int nj = 0; nj < 4; nj++) {
            const int col = h * DKc + wn * 32 + nj * 8 + tc;
            const float v00 = acc[mi][nj][0], v01 = acc[mi][nj][1];
            const float v10 = acc[mi][nj][2], v11 = acc[mi][nj][3];
            const __half h00 = __float2half_rn(v00);
            const __half h01 = __float2half_rn(v01);
            const __half h10 = __float2half_rn(v10);
            const __half h11 = __float2half_rn(v11);
            *(__half2*)(Ch + (size_t)r * Dc + col) = __halves2half2(h00, h01);
            *(__half2*)(Cl + (size_t)r * Dc + col) = __halves2half2(
                __float2half_rn(v00 - __half2float(h00)),
                __float2half_rn(v01 - __half2float(h01)));
            *(__half2*)(Ch + (size_t)(r + 8) * Dc + col) = __halves2half2(h10, h11);
            *(__half2*)(Cl + (size_t)(r + 8) * Dc + col) = __halves2half2(
                __float2half_rn(v10 - __half2float(h10)),
                __float2half_rn(v11 - __half2float(h11)));
        }
    }
}

// ---------------------------------------------------------------------------
extern "C" void kernel_launch(void* const* d_in, const int* in_sizes, int n_in,
                              void* d_out, int out_size)
{
    (void)in_sizes; (void)n_in; (void)out_size;

    const float* Q     = (const float*)d_in[0];
    const float* prev  = (const float*)d_in[1];
    const float* Wq    = (const float*)d_in[2];
    const float* bq    = (const float*)d_in[3];
    const float* Wk    = (const float*)d_in[4];
    const float* bk    = (const float*)d_in[5];
    const float* Wv    = (const float*)d_in[6];
    const float* bv    = (const float*)d_in[7];
    const float* Wg    = (const float*)d_in[8];
    const float* bg    = (const float*)d_in[9];
    const float* Wo    = (const float*)d_in[10];
    const float* bo    = (const float*)d_in[11];
    const float* scale = (const float*)d_in[12];

    float* out    = (float*)d_out;
    float* attn   = out + OUT_ELEMS;
    float* scores = attn + ATTN_ELEMS;

    float* gb;
    __half *ah, *al, *wh, *wl, *qh, *ql, *kh, *kl, *vh, *vl;
    cudaGetSymbolAddress((void**)&gb, g_gt);
    cudaGetSymbolAddress((void**)&ah, g_ah);
    cudaGetSymbolAddress((void**)&al, g_al);
    cudaGetSymbolAddress((void**)&wh, g_wh);
    cudaGetSymbolAddress((void**)&wl, g_wl);
    cudaGetSymbolAddress((void**)&qh, g_qh);
    cudaGetSymbolAddress((void**)&ql, g_ql);
    cudaGetSymbolAddress((void**)&kh, g_kh);
    cudaGetSymbolAddress((void**)&kl, g_kl);
    cudaGetSymbolAddress((void**)&vh, g_vh);
    cudaGetSymbolAddress((void**)&vl, g_vl);

    cudaFuncSetAttribute((const void*)gemm_mma<0, 3>, cudaFuncAttributeMaxDynamicSharedMemorySize, GEMM_SMEM);
    cudaFuncSetAttribute((const void*)gemm_mma<1, 3>, cudaFuncAttributeMaxDynamicSharedMemorySize, GEMM_SMEM);
    cudaFuncSetAttribute((const void*)gemm_mma<0, 2>, cudaFuncAttributeMaxDynamicSharedMemorySize, GEMM_SMEM);
    cudaFuncSetAttribute((const void*)scores_tc,      cudaFuncAttributeMaxDynamicSharedMemorySize, SC_SMEM);
    cudaFuncSetAttribute((const void*)ctx_tc,         cudaFuncAttributeMaxDynamicSharedMemorySize, CT_SMEM);

    const dim3 tblk(32, 8);
    const long long nQ4 = (long long)Mc * Dc / 4;

    // split input activations into fp16 hi/lo
    split_kernel<<<(int)(nQ4 / 256), 256>>>(Q, ah, al, nQ4);

    // q/k/v projections -> fp16 hi/lo directly (3-pass)
    transpose_split<<<dim3(Dc / 32, Dc / 32), tblk>>>(Wq, wh, wl, Dc, Dc);
    gemm_mma<1, 3><<<dim3(Dc / 128, Mc / 128), 256, GEMM_SMEM>>>(ah, al, wh, wl, bq, nullptr, qh, ql, Dc, Dc);
    transpose_split<<<dim3(Dc / 32, Dc / 32), tblk>>>(Wk, wh, wl, Dc, Dc);
    gemm_mma<1, 3><<<dim3(Dc / 128, Mc / 128), 256, GEMM_SMEM>>>(ah, al, wh, wl, bk, nullptr, kh, kl, Dc, Dc);
    transpose_split<<<dim3(Dc / 32, Dc / 32), tblk>>>(Wv, wh, wl, Dc, Dc);
    gemm_mma<1, 3><<<dim3(Dc / 128, Mc / 128), 256, GEMM_SMEM>>>(ah, al, wh, wl, bv, nullptr, vh, vl, Dc, Dc);
    // gate projection (N = 8192) -> fp32, 2-pass (weight-lo dropped; post-softmax path)
    transpose_split<<<dim3(Gc / 32, Dc / 32), tblk>>>(Wg, wh, wl, Dc, Gc);
    gemm_mma<0, 2><<<dim3(Gc / 128, Mc / 128), 256, GEMM_SMEM>>>(ah, al, wh, wl, bg, gb, nullptr, nullptr, Gc, Dc);

    // scores = q k^T * scale + prev (3-pass)
    scores_tc<<<dim3(4, 4, Bc * Hc), 256, SC_SMEM>>>(prev, scale, scores);
    // attn = gate * softmax(scores)
    softmax_gate_kernel<<<(Bc * Hc * Sc) / 8, 256>>>(attn, scores);
    // ctx = attn @ v (3-pass) -> fp16 hi/lo into ah/al
    ctx_tc<<<dim3(4, Bc * Hc), 256, CT_SMEM>>>(attn, ah, al);

    // out = ctx @ Wo + bo (3-pass)
    transpose_split<<<dim3(Dc / 32, Dc / 32), tblk>>>(Wo, wh, wl, Dc, Dc);
    gemm_mma<0, 3><<<dim3(Dc / 128, Mc / 128), 256, GEMM_SMEM>>>(ah, al, wh, wl, bo, out, nullptr, nullptr, Dc, Dc);
}

// round 9
// speedup vs baseline: 3.8979x; 1.2189x over previous
#include <cuda_runtime.h>
#include <cuda_fp16.h>
#include <cstdint>
#include <cstddef>

// Problem constants
#define Bc  16
#define Sc  512
#define Dc  1024
#define Hc  16
#define DKc 64
#define Mc  8192   // B*S
#define Gc  8192   // H*S

#define OUT_ELEMS  8388608LL
#define ATTN_ELEMS 67108864LL

// -------------------- device scratch (static globals; no allocs) -----------
__device__ float g_gt [(size_t)Mc * Gc];      // gate [b*S+s][h*S+k] fp32
__device__ __half g_ah[(size_t)Mc * Dc];      // activation hi / later ctx hi
__device__ __half g_al[(size_t)Mc * Dc];      // activation lo / later ctx lo
__device__ __half g_wh[(size_t)Gc * Dc];      // weight^T hi [N,K]
__device__ __half g_wl[(size_t)Gc * Dc];      // weight^T lo
__device__ __half g_qh[(size_t)Mc * Dc];
__device__ __half g_ql[(size_t)Mc * Dc];
__device__ __half g_kh[(size_t)Mc * Dc];
__device__ __half g_kl[(size_t)Mc * Dc];
__device__ __half g_vh[(size_t)Mc * Dc];
__device__ __half g_vl[(size_t)Mc * Dc];

// ===================== PTX helpers (sm_80-level only) ======================
__device__ __forceinline__ uint32_t smem_u32(const void* p) {
    uint32_t a;
    asm("{ .reg .u64 t; cvta.to.shared.u64 t, %1; cvt.u32.u64 %0, t; }" : "=r"(a) : "l"(p));
    return a;
}
__device__ __forceinline__ void cp16(uint32_t smem, const void* g) {
    asm volatile("cp.async.cg.shared.global [%0], [%1], 16;\n" :: "r"(smem), "l"(g));
}
#define CP_COMMIT() asm volatile("cp.async.commit_group;" ::: "memory")
#define CP_WAIT0()  asm volatile("cp.async.wait_group 0;" ::: "memory")

#define LDSM4(r0, r1, r2, r3, addr) \
    asm volatile("ldmatrix.sync.aligned.m8n8.x4.shared.b16 {%0,%1,%2,%3}, [%4];" \
        : "=r"(r0), "=r"(r1), "=r"(r2), "=r"(r3) : "r"(addr))
#define LDSM4T(r0, r1, r2, r3, addr) \
    asm volatile("ldmatrix.sync.aligned.m8n8.x4.trans.shared.b16 {%0,%1,%2,%3}, [%4];" \
        : "=r"(r0), "=r"(r1), "=r"(r2), "=r"(r3) : "r"(addr))

#define MMA_F16(d, a, b) \
    asm volatile("mma.sync.aligned.m16n8k16.row.col.f32.f16.f16.f32 " \
        "{%0,%1,%2,%3},{%4,%5,%6,%7},{%8,%9},{%0,%1,%2,%3};" \
        : "+f"((d)[0]), "+f"((d)[1]), "+f"((d)[2]), "+f"((d)[3]) \
        : "r"((a)[0]), "r"((a)[1]), "r"((a)[2]), "r"((a)[3]), \
          "r"((b)[0]), "r"((b)[1]))

// ===================== conversion kernels ==================================
__global__ void __launch_bounds__(256)
split_kernel(const float* __restrict__ x, __half* __restrict__ hi,
             __half* __restrict__ lo, long long n4)
{
    long long i = ((long long)blockIdx.x * 256 + threadIdx.x);
    if (i >= n4) return;
    const float4 v = ((const float4*)x)[i];
    const __half h0 = __float2half_rn(v.x);
    const __half h1 = __float2half_rn(v.y);
    const __half h2 = __float2half_rn(v.z);
    const __half h3 = __float2half_rn(v.w);
    ((__half2*)hi)[i * 2 + 0] = __halves2half2(h0, h1);
    ((__half2*)hi)[i * 2 + 1] = __halves2half2(h2, h3);
    ((__half2*)lo)[i * 2 + 0] = __halves2half2(
        __float2half_rn(v.x - __half2float(h0)),
        __float2half_rn(v.y - __half2float(h1)));
    ((__half2*)lo)[i * 2 + 1] = __halves2half2(
        __float2half_rn(v.z - __half2float(h2)),
        __float2half_rn(v.w - __half2float(h3)));
}

// W[K][N] fp32 -> T[N][K] fp16 hi/lo
__global__ void __launch_bounds__(256)
transpose_split(const float* __restrict__ W, __half* __restrict__ Th,
                __half* __restrict__ Tl, int K, int N)
{
    __shared__ float t[32][33];
    const int n0 = blockIdx.x * 32, k0 = blockIdx.y * 32;
    const int tx = threadIdx.x, ty = threadIdx.y;  // (32, 8)
    #pragma unroll
    for (int p = 0; p < 4; p++) {
        const int kk = ty + p * 8;
        t[kk][tx] = W[(size_t)(k0 + kk) * N + n0 + tx];
    }
    __syncthreads();
    #pragma unroll
    for (int p = 0; p < 4; p++) {
        const int nn = ty + p * 8;
        const float v = t[tx][nn];
        const __half h = __float2half_rn(v);
        Th[(size_t)(n0 + nn) * K + k0 + tx] = h;
        Tl[(size_t)(n0 + nn) * K + k0 + tx] = __float2half_rn(v - __half2float(h));
    }
}

// ===================== mma.sync split-fp16 GEMM ============================
// PASSES==3: Ah@Bh + Ah@Bl + Al@Bh.  PASSES==2: Ah@Bh + Al@Bh.  PASSES==1: Ah@Bh.
// MODE 0: C fp32 (+bias). MODE 1: write fp16 hi/lo split of (acc+bias).
#define RS 80
#define TILE_B   (128 * RS)
#define STAGE_B  (4 * TILE_B)
#define GEMM_SMEM (2 * STAGE_B)      // 81920

template<int MODE, int PASSES>
__global__ void __launch_bounds__(256, 2)
gemm_mma(const __half* __restrict__ Ah, const __half* __restrict__ Al,
         const __half* __restrict__ Bh, const __half* __restrict__ Bl,
         const float* __restrict__ bias, float* __restrict__ C,
         __half* __restrict__ Ch, __half* __restrict__ Cl,
         int Ntot, int K)
{
    extern __shared__ char dsm[];
    const uint32_t sb0 = smem_u32(dsm);
    const int tid  = threadIdx.x;
    const int lane = tid & 31;
    const int wid  = tid >> 5;
    const int wm   = wid & 3;
    const int wn   = wid >> 2;
    const int m0   = blockIdx.y * 128;
    const int n0   = blockIdx.x * 128;

    const size_t Kb = (size_t)K * 2;
    const int NK = K >> 5;

    const char* pAh = (const char*)Ah + (size_t)m0 * Kb;
    const char* pAl = (const char*)Al + (size_t)m0 * Kb;
    const char* pBh = (const char*)Bh + (size_t)n0 * Kb;
    const char* pBl = (const char*)Bl + (size_t)n0 * Kb;

    auto load_stage = [&](int kt, int s) {
        const uint32_t sb = sb0 + (uint32_t)s * STAGE_B;
        const size_t kb = (size_t)kt * 64;
        #pragma unroll
        for (int i = 0; i < 2; i++) {
            const int c   = tid + i * 256;
            const int row = c >> 2;
            const int seg = (c & 3) * 16;
            const uint32_t so = (uint32_t)(row * RS + seg);
            const size_t go = (size_t)row * Kb + kb + seg;
            cp16(sb + so, pAh + go);
            if (PASSES >= 2) cp16(sb + TILE_B + so, pAl + go);
            cp16(sb + 2 * TILE_B + so, pBh + go);
            if (PASSES == 3) cp16(sb + 3 * TILE_B + so, pBl + go);
        }
    };

    const uint32_t aRow  = (uint32_t)(wm * 32 + (lane & 15));
    const uint32_t aByte = (uint32_t)((lane >> 4) * 16);
    const uint32_t bRow  = (uint32_t)(wn * 64 + (lane & 7) + ((lane >> 4) & 1) * 8);
    const uint32_t bByte = (uint32_t)(((lane >> 3) & 1) * 16);

    float acc[2][8][4] = {};

    load_stage(0, 0); CP_COMMIT();

    for (int kt = 0; kt < NK; kt++) {
        const int s = kt & 1;
        CP_WAIT0();
        __syncthreads();
        if (kt + 1 < NK) { load_stage(kt + 1, s ^ 1); CP_COMMIT(); }

        const uint32_t sb = sb0 + (uint32_t)s * STAGE_B;

        #pragma unroll
        for (int kk = 0; kk < 2; kk++) {
            uint32_t ah[2][4], al[2][4];
            #pragma unroll
            for (int mi = 0; mi < 2; mi++) {
                const uint32_t ad = sb + (aRow + mi * 16) * RS + kk * 32 + aByte;
                LDSM4(ah[mi][0], ah[mi][1], ah[mi][2], ah[mi][3], ad);
                if (PASSES >= 2)
                    LDSM4(al[mi][0], al[mi][1], al[mi][2], al[mi][3], ad + TILE_B);
            }
            #pragma unroll
            for (int hf = 0; hf < 2; hf++) {
                uint32_t bh[4][2], bl[4][2];
                #pragma unroll
                for (int p = 0; p < 2; p++) {
                    const uint32_t bd = sb + 2 * TILE_B +
                        (bRow + (hf * 2 + p) * 16) * RS + kk * 32 + bByte;
                    uint32_t t0, t1, t2, t3;
                    LDSM4(t0, t1, t2, t3, bd);
                    bh[2 * p][0] = t0; bh[2 * p][1] = t1;
                    bh[2 * p + 1][0] = t2; bh[2 * p + 1][1] = t3;
                    if (PASSES == 3) {
                        LDSM4(t0, t1, t2, t3, bd + TILE_B);
                        bl[2 * p][0] = t0; bl[2 * p][1] = t1;
                        bl[2 * p + 1][0] = t2; bl[2 * p + 1][1] = t3;
                    }
                }
                #pragma unroll
                for (int mi = 0; mi < 2; mi++)
                    #pragma unroll
                    for (int nj = 0; nj < 4; nj++) {
                        float* d = acc[mi][hf * 4 + nj];
                        MMA_F16(d, ah[mi], bh[nj]);
                        if (PASSES == 3) MMA_F16(d, ah[mi], bl[nj]);
                        if (PASSES >= 2) MMA_F16(d, al[mi], bh[nj]);
                    }
            }
        }
    }

    const int trow = lane >> 2;
    const int tc   = (lane & 3) * 2;
    #pragma unroll
    for (int mi = 0; mi < 2; mi++) {
        const int r = m0 + wm * 32 + mi * 16 + trow;
        #pragma unroll
        for (int ni = 0; ni < 8; ni++) {
            const int col = n0 + wn * 64 + ni * 8 + tc;
            const float2 bv = *(const float2*)(bias + col);
            const float v00 = acc[mi][ni][0] + bv.x;
            const float v01 = acc[mi][ni][1] + bv.y;
            const float v10 = acc[mi][ni][2] + bv.x;
            const float v11 = acc[mi][ni][3] + bv.y;
            if (MODE == 0) {
                float2 o0 = {v00, v01}, o1 = {v10, v11};
                *(float2*)(C + (size_t)r * Ntot + col) = o0;
                *(float2*)(C + (size_t)(r + 8) * Ntot + col) = o1;
            } else {
                const __half h00 = __float2half_rn(v00);
                const __half h01 = __float2half_rn(v01);
                const __half h10 = __float2half_rn(v10);
                const __half h11 = __float2half_rn(v11);
                *(__half2*)(Ch + (size_t)r * Ntot + col) = __halves2half2(h00, h01);
                *(__half2*)(Cl + (size_t)r * Ntot + col) = __halves2half2(
                    __float2half_rn(v00 - __half2float(h00)),
                    __float2half_rn(v01 - __half2float(h01)));
                *(__half2*)(Ch + (size_t)(r + 8) * Ntot + col) = __halves2half2(h10, h11);
                *(__half2*)(Cl + (size_t)(r + 8) * Ntot + col) = __halves2half2(
                    __float2half_rn(v10 - __half2float(h10)),
                    __float2half_rn(v11 - __half2float(h11)));
            }
        }
    }
}

// ===================== scores via mma: q k^T * scale + prev ================
// grid (4, 4, 256): 128x128 tile per block per (b,h). K = 64. 3-pass.
#define RS2 144
#define SC_TILE (128 * RS2)
#define SC_SMEM (4 * SC_TILE)         // 73728: Qh | Ql | Kh | Kl

__global__ void __launch_bounds__(256, 2)
scores_tc(const float* __restrict__ prev, const float* __restrict__ scale_p,
          float* __restrict__ scores)
{
    extern __shared__ char dsm[];
    const uint32_t sb = smem_u32(dsm);
    const int tid  = threadIdx.x;
    const int lane = tid & 31;
    const int wid  = tid >> 5;
    const int wm   = wid & 3;
    const int wn   = wid >> 2;
    const int bh = blockIdx.z;
    const int b  = bh >> 4;
    const int h  = bh & 15;
    const int q0 = blockIdx.y * 128;
    const int n0 = blockIdx.x * 128;

    const char* pQh = (const char*)g_qh + ((size_t)(b * Sc + q0) * Dc + h * DKc) * 2;
    const char* pQl = (const char*)g_ql + ((size_t)(b * Sc + q0) * Dc + h * DKc) * 2;
    const char* pKh = (const char*)g_kh + ((size_t)(b * Sc + n0) * Dc + h * DKc) * 2;
    const char* pKl = (const char*)g_kl + ((size_t)(b * Sc + n0) * Dc + h * DKc) * 2;
    #pragma unroll
    for (int i = 0; i < 4; i++) {
        const int c   = tid + i * 256;
        const int row = c >> 3;
        const int seg = (c & 7) * 16;
        const uint32_t so = (uint32_t)(row * RS2 + seg);
        const size_t go = (size_t)row * (Dc * 2) + seg;
        cp16(sb + so,               pQh + go);
        cp16(sb + SC_TILE + so,     pQl + go);
        cp16(sb + 2 * SC_TILE + so, pKh + go);
        cp16(sb + 3 * SC_TILE + so, pKl + go);
    }
    CP_COMMIT(); CP_WAIT0();
    __syncthreads();

    const uint32_t aRow  = (uint32_t)(wm * 32 + (lane & 15));
    const uint32_t aByte = (uint32_t)((lane >> 4) * 16);
    const uint32_t bRow  = (uint32_t)(wn * 64 + (lane & 7) + ((lane >> 4) & 1) * 8);
    const uint32_t bByte = (uint32_t)(((lane >> 3) & 1) * 16);

    float acc[2][8][4] = {};

    #pragma unroll
    for (int kk = 0; kk < 4; kk++) {
        uint32_t ah[2][4], al[2][4];
        #pragma unroll
        for (int mi = 0; mi < 2; mi++) {
            const uint32_t ad = sb + (aRow + mi * 16) * RS2 + kk * 32 + aByte;
            LDSM4(ah[mi][0], ah[mi][1], ah[mi][2], ah[mi][3], ad);
            LDSM4(al[mi][0], al[mi][1], al[mi][2], al[mi][3], ad + SC_TILE);
        }
        #pragma unroll
        for (int hf = 0; hf < 2; hf++) {
            uint32_t bhr[4][2], blr[4][2];
            #pragma unroll
            for (int p = 0; p < 2; p++) {
                const uint32_t bd = sb + 2 * SC_TILE +
                    (bRow + (hf * 2 + p) * 16) * RS2 + kk * 32 + bByte;
                uint32_t t0, t1, t2, t3;
                LDSM4(t0, t1, t2, t3, bd);
                bhr[2 * p][0] = t0; bhr[2 * p][1] = t1;
                bhr[2 * p + 1][0] = t2; bhr[2 * p + 1][1] = t3;
                LDSM4(t0, t1, t2, t3, bd + SC_TILE);
                blr[2 * p][0] = t0; blr[2 * p][1] = t1;
                blr[2 * p + 1][0] = t2; blr[2 * p + 1][1] = t3;
            }
            #pragma unroll
            for (int mi = 0; mi < 2; mi++)
                #pragma unroll
                for (int nj = 0; nj < 4; nj++) {
                    float* d = acc[mi][hf * 4 + nj];
                    MMA_F16(d, ah[mi], bhr[nj]);
                    MMA_F16(d, ah[mi], blr[nj]);
                    MMA_F16(d, al[mi], bhr[nj]);
                }
        }
    }

    const float scale = *scale_p;
    const int trow = lane >> 2;
    const int tc   = (lane & 3) * 2;
    const size_t base = ((size_t)(b * Hc + h) * Sc) * Sc;
    #pragma unroll
    for (int mi = 0; mi < 2; mi++) {
        const int r = q0 + wm * 32 + mi * 16 + trow;
        #pragma unroll
        for (int ni = 0; ni < 8; ni++) {
            const int col = n0 + wn * 64 + ni * 8 + tc;
            const size_t o0 = base + (size_t)r * Sc + col;
            const size_t o1 = base + (size_t)(r + 8) * Sc + col;
            const float2 p0 = *(const float2*)(prev + o0);
            const float2 p1 = *(const float2*)(prev + o1);
            float2 w0, w1;
            w0.x = fmaf(acc[mi][ni][0], scale, p0.x);
            w0.y = fmaf(acc[mi][ni][1], scale, p0.y);
            w1.x = fmaf(acc[mi][ni][2], scale, p1.x);
            w1.y = fmaf(acc[mi][ni][3], scale, p1.y);
            *(float2*)(scores + o0) = w0;
            *(float2*)(scores + o1) = w1;
        }
    }
}

// ===================== softmax * gate ======================================
__global__ void __launch_bounds__(256)
softmax_gate_kernel(float* __restrict__ attn, const float* __restrict__ scores)
{
    const int warp = threadIdx.x >> 5;
    const int lane = threadIdx.x & 31;
    const long long row = (long long)blockIdx.x * 8 + warp;

    const float* srow = scores + row * Sc;
    float*       arow = attn   + row * Sc;

    const int b  = (int)(row >> 13);
    const int hq = (int)(row & 8191);
    const int h  = hq >> 9;
    const int q  = hq & 511;
    const float* grow = g_gt + (size_t)(b * Sc + q) * Gc + (size_t)h * Sc;

    float4 x[4];
    float mx = -3.402823466e38f;
    #pragma unroll
    for (int t = 0; t < 4; t++) {
        x[t] = *(const float4*)(srow + t * 128 + lane * 4);
        mx = fmaxf(mx, fmaxf(fmaxf(x[t].x, x[t].y), fmaxf(x[t].z, x[t].w)));
    }
    #pragma unroll
    for (int o = 16; o > 0; o >>= 1)
        mx = fmaxf(mx, __shfl_xor_sync(0xffffffffu, mx, o));

    float sum = 0.0f;
    #pragma unroll
    for (int t = 0; t < 4; t++) {
        x[t].x = __expf(x[t].x - mx);
        x[t].y = __expf(x[t].y - mx);
        x[t].z = __expf(x[t].z - mx);
        x[t].w = __expf(x[t].w - mx);
        sum += (x[t].x + x[t].y) + (x[t].z + x[t].w);
    }
    #pragma unroll
    for (int o = 16; o > 0; o >>= 1)
        sum += __shfl_xor_sync(0xffffffffu, sum, o);
    const float inv = 1.0f / sum;

    #pragma unroll
    for (int t = 0; t < 4; t++) {
        const float4 gv = *(const float4*)(grow + t * 128 + lane * 4);
        float4 o;
        o.x = gv.x * x[t].x * inv;
        o.y = gv.y * x[t].y * inv;
        o.z = gv.z * x[t].z * inv;
        o.w = gv.w * x[t].w * inv;
        *(float4*)(arow + t * 128 + lane * 4) = o;
    }
}

// ===================== ctx = attn @ v via mma (2-pass: v-lo dropped) =======
#define CT_A    (128 * RS2)
#define CT_V    (64 * RS2)
#define CT_SMEM (2 * CT_A + CT_V)   // Ah | Al | Vh

__global__ void __launch_bounds__(256, 2)
ctx_tc(const float* __restrict__ attn,
       __half* __restrict__ Ch, __half* __restrict__ Cl)
{
    extern __shared__ char dsm[];
    const uint32_t sA = smem_u32(dsm);
    const uint32_t sV = sA + 2 * CT_A;
    const int tid  = threadIdx.x;
    const int lane = tid & 31;
    const int wid  = tid >> 5;
    const int wm   = wid & 3;
    const int wn   = wid >> 2;
    const int bh = blockIdx.y;
    const int b  = bh >> 4;
    const int h  = bh & 15;
    const int q0 = blockIdx.x * 128;

    const size_t abase = ((size_t)(b * Hc + h) * Sc + q0) * Sc;
    const char* pVh = (const char*)g_vh + ((size_t)(b * Sc) * Dc + h * DKc) * 2;

    const uint32_t aRow  = (uint32_t)(wm * 32 + (lane & 15));
    const uint32_t aByte = (uint32_t)((lane >> 4) * 16);
    const uint32_t vRowL = (uint32_t)(lane & 15);
    const uint32_t vColB = (uint32_t)((wn * 32 + (lane >> 4) * 8) * 2);

    float acc[2][4][4] = {};

    for (int kt = 0; kt < 8; kt++) {
        __syncthreads();
        #pragma unroll
        for (int i = 0; i < 2; i++) {
            const int c   = tid + i * 256;
            const int row = c >> 3;
            const int seg = (c & 7) * 16;
            const uint32_t so = (uint32_t)(row * RS2 + seg);
            const size_t go = (size_t)(kt * 64 + row) * (Dc * 2) + seg;
            cp16(sV + so, pVh + go);
        }
        CP_COMMIT();
        #pragma unroll
        for (int i = 0; i < 8; i++) {
            const int c   = tid + i * 256;
            const int row = c >> 4;
            const int f4  = c & 15;
            const float4 v = *(const float4*)(attn + abase + (size_t)row * Sc + kt * 64 + f4 * 4);
            const __half h0 = __float2half_rn(v.x);
            const __half h1 = __float2half_rn(v.y);
            const __half h2 = __float2half_rn(v.z);
            const __half h3 = __float2half_rn(v.w);
            const __half2 ph0 = __halves2half2(h0, h1);
            const __half2 ph1 = __halves2half2(h2, h3);
            const __half2 pl0 = __halves2half2(
                __float2half_rn(v.x - __half2float(h0)),
                __float2half_rn(v.y - __half2float(h1)));
            const __half2 pl1 = __halves2half2(
                __float2half_rn(v.z - __half2float(h2)),
                __float2half_rn(v.w - __half2float(h3)));
            const uint32_t so = (uint32_t)(row * RS2 + f4 * 8);
            *(uint32_t*)(dsm + (so))            = *(uint32_t*)&ph0;
            *(uint32_t*)(dsm + (so + 4))        = *(uint32_t*)&ph1;
            *(uint32_t*)(dsm + (CT_A + so))     = *(uint32_t*)&pl0;
            *(uint32_t*)(dsm + (CT_A + so + 4)) = *(uint32_t*)&pl1;
        }
        CP_WAIT0();
        __syncthreads();

        #pragma unroll
        for (int kk = 0; kk < 4; kk++) {
            uint32_t ah[2][4], al[2][4];
            #pragma unroll
            for (int mi = 0; mi < 2; mi++) {
                const uint32_t ad = sA + (aRow + mi * 16) * RS2 + kk * 32 + aByte;
                LDSM4(ah[mi][0], ah[mi][1], ah[mi][2], ah[mi][3], ad);
                LDSM4(al[mi][0], al[mi][1], al[mi][2], al[mi][3], ad + CT_A);
            }
            uint32_t bh_[4][2];
            #pragma unroll
            for (int p = 0; p < 2; p++) {
                const uint32_t vd = sV + (kk * 16 + vRowL) * RS2 + vColB + p * 32;
                uint32_t t0, t1, t2, t3;
                LDSM4T(t0, t1, t2, t3, vd);
                bh_[2 * p][0] = t0; bh_[2 * p][1] = t1;
                bh_[2 * p + 1][0] = t2; bh_[2 * p + 1][1] = t3;
            }
            #pragma unroll
            for (int mi = 0; mi < 2; mi++)
                #pragma unroll
                for (int nj = 0; nj < 4; nj++) {
                    float* d = acc[mi][nj];
                    MMA_F16(d, ah[mi], bh_[nj]);
                    MMA_F16(d, al[mi], bh_[nj]);
                }
        }
    }

    const int trow = lane >> 2;
    const int tc   = (lane & 3) * 2;
    #pragma unroll
    for (int mi = 0; mi < 2; mi++) {
        const int r = b * Sc + q0 + wm * 32 + mi * 16 + trow;
        #pragma unroll
        for (int nj = 0; nj < 4; nj++) {
            const int col = h * DKc + wn * 32 + nj * 8 + tc;
            const float v00 = acc[mi][nj][0], v01 = acc[mi][nj][1];
            const float v10 = acc[mi][nj][2], v11 = acc[mi][nj][3];
            const __half h00 = __float2half_rn(v00);
            const __half h01 = __float2half_rn(v01);
            const __half h10 = __float2half_rn(v10);
            const __half h11 = __float2half_rn(v11);
            *(__half2*)(Ch + (size_t)r * Dc + col) = __halves2half2(h00, h01);
            *(__half2*)(Cl + (size_t)r * Dc + col) = __halves2half2(
                __float2half_rn(v00 - __half2float(h00)),
                __float2half_rn(v01 - __half2float(h01)));
            *(__half2*)(Ch + (size_t)(r + 8) * Dc + col) = __halves2half2(h10, h11);
            *(__half2*)(Cl + (size_t)(r + 8) * Dc + col) = __halves2half2(
                __float2half_rn(v10 - __half2float(h10)),
                __float2half_rn(v11 - __half2float(h11)));
        }
    }
}

// ---------------------------------------------------------------------------
extern "C" void kernel_launch(void* const* d_in, const int* in_sizes, int n_in,
                              void* d_out, int out_size)
{
    (void)in_sizes; (void)n_in; (void)out_size;

    const float* Q     = (const float*)d_in[0];
    const float* prev  = (const float*)d_in[1];
    const float* Wq    = (const float*)d_in[2];
    const float* bq    = (const float*)d_in[3];
    const float* Wk    = (const float*)d_in[4];
    const float* bk    = (const float*)d_in[5];
    const float* Wv    = (const float*)d_in[6];
    const float* bv    = (const float*)d_in[7];
    const float* Wg    = (const float*)d_in[8];
    const float* bg    = (const float*)d_in[9];
    const float* Wo    = (const float*)d_in[10];
    const float* bo    = (const float*)d_in[11];
    const float* scale = (const float*)d_in[12];

    float* out    = (float*)d_out;
    float* attn   = out + OUT_ELEMS;
    float* scores = attn + ATTN_ELEMS;

    float* gb;
    __half *ah, *al, *wh, *wl, *qh, *ql, *kh, *kl, *vh, *vl;
    cudaGetSymbolAddress((void**)&gb, g_gt);
    cudaGetSymbolAddress((void**)&ah, g_ah);
    cudaGetSymbolAddress((void**)&al, g_al);
    cudaGetSymbolAddress((void**)&wh, g_wh);
    cudaGetSymbolAddress((void**)&wl, g_wl);
    cudaGetSymbolAddress((void**)&qh, g_qh);
    cudaGetSymbolAddress((void**)&ql, g_ql);
    cudaGetSymbolAddress((void**)&kh, g_kh);
    cudaGetSymbolAddress((void**)&kl, g_kl);
    cudaGetSymbolAddress((void**)&vh, g_vh);
    cudaGetSymbolAddress((void**)&vl, g_vl);

    cudaFuncSetAttribute((const void*)gemm_mma<0, 3>, cudaFuncAttributeMaxDynamicSharedMemorySize, GEMM_SMEM);
    cudaFuncSetAttribute((const void*)gemm_mma<1, 3>, cudaFuncAttributeMaxDynamicSharedMemorySize, GEMM_SMEM);
    cudaFuncSetAttribute((const void*)gemm_mma<0, 2>, cudaFuncAttributeMaxDynamicSharedMemorySize, GEMM_SMEM);
    cudaFuncSetAttribute((const void*)gemm_mma<0, 1>, cudaFuncAttributeMaxDynamicSharedMemorySize, GEMM_SMEM);
    cudaFuncSetAttribute((const void*)scores_tc,      cudaFuncAttributeMaxDynamicSharedMemorySize, SC_SMEM);
    cudaFuncSetAttribute((const void*)ctx_tc,         cudaFuncAttributeMaxDynamicSharedMemorySize, CT_SMEM);

    const dim3 tblk(32, 8);
    const long long nQ4 = (long long)Mc * Dc / 4;

    // split input activations into fp16 hi/lo
    split_kernel<<<(int)(nQ4 / 256), 256>>>(Q, ah, al, nQ4);

    // q/k/v projections -> fp16 hi/lo directly (3-pass)
    transpose_split<<<dim3(Dc / 32, Dc / 32), tblk>>>(Wq, wh, wl, Dc, Dc);
    gemm_mma<1, 3><<<dim3(Dc / 128, Mc / 128), 256, GEMM_SMEM>>>(ah, al, wh, wl, bq, nullptr, qh, ql, Dc, Dc);
    transpose_split<<<dim3(Dc / 32, Dc / 32), tblk>>>(Wk, wh, wl, Dc, Dc);
    gemm_mma<1, 3><<<dim3(Dc / 128, Mc / 128), 256, GEMM_SMEM>>>(ah, al, wh, wl, bk, nullptr, kh, kl, Dc, Dc);
    transpose_split<<<dim3(Dc / 32, Dc / 32), tblk>>>(Wv, wh, wl, Dc, Dc);
    gemm_mma<1, 3><<<dim3(Dc / 128, Mc / 128), 256, GEMM_SMEM>>>(ah, al, wh, wl, bv, nullptr, vh, vl, Dc, Dc);
    // gate projection (N = 8192) -> fp32, 1-pass (post-softmax path; error non-compounding)
    transpose_split<<<dim3(Gc / 32, Dc / 32), tblk>>>(Wg, wh, wl, Dc, Gc);
    gemm_mma<0, 1><<<dim3(Gc / 128, Mc / 128), 256, GEMM_SMEM>>>(ah, al, wh, wl, bg, gb, nullptr, nullptr, Gc, Dc);

    // scores = q k^T * scale + prev (3-pass, pristine)
    scores_tc<<<dim3(4, 4, Bc * Hc), 256, SC_SMEM>>>(prev, scale, scores);
    // attn = gate * softmax(scores)
    softmax_gate_kernel<<<(Bc * Hc * Sc) / 8, 256>>>(attn, scores);
    // ctx = attn @ v (2-pass) -> fp16 hi/lo into ah/al
    ctx_tc<<<dim3(4, Bc * Hc), 256, CT_SMEM>>>(attn, ah, al);

    // out = ctx @ Wo + bo (2-pass: weight-lo dropped)
    transpose_split<<<dim3(Dc / 32, Dc / 32), tblk>>>(Wo, wh, wl, Dc, Dc);
    gemm_mma<0, 2><<<dim3(Dc / 128, Mc / 128), 256, GEMM_SMEM>>>(ah, al, wh, wl, bo, out, nullptr, nullptr, Dc, Dc);
}